// round 9
// baseline (speedup 1.0000x reference)
#include <cuda_runtime.h>
#include <math.h>
#include <float.h>

#define BB 64
#define CC 100
#define KK 5
#define NN (BB*CC*KK)      // 32000
#define NBINS 2048
#define NLB 64             // Team L blocks
#define NBLK 128
#define NTHR 256
#define NPB (NN/NLB)       // 500 elements per L block
#define NAB 40             // blocks active in Phase A (320 warp tasks / 8)
#define DMINF (-8.0f)
#define INVWF 128.0f       // NBINS / 16

// ---------------- device scratch (no allocs allowed) ----------------
__device__ float4 g_pack[NN];          // (t, s, d, 0)
__device__ float2 g_hist2[NBINS];      // (sumT, sumS) via float atomics
__device__ float  g_tk[KK*BB*CC], g_sk[KK*BB*CC];   // [k][b][c]
__device__ double g_tt, g_ss, g_ts, g_kl[KK], g_ce, g_l1, g_sub;
__device__ unsigned g_adone;           // Phase-A completion counter
__device__ unsigned g_done;            // last-block-out counter

__device__ __forceinline__ int binOf(float x){
    int j = (int)floorf((x - DMINF) * INVWF);
    return min(max(j, 0), NBINS-1);    // clamp safe: extreme-|d| elements have tiny t or s
}

__device__ __forceinline__ float blockSum(float v, float* shR){
    int lane = threadIdx.x & 31, w = threadIdx.x >> 5;
    #pragma unroll
    for (int o=16;o;o>>=1) v += __shfl_down_sync(0xffffffffu, v, o);
    if (lane==0) shR[w] = v;
    __syncthreads();
    float r = 0.f;
    if (threadIdx.x==0){
        #pragma unroll
        for (int i=0;i<NTHR/32;i++) r += shR[i];
    }
    __syncthreads();
    return r;   // valid on tid 0 only
}

__global__ void __launch_bounds__(NTHR)
fused_kernel(const float* __restrict__ ls, const float* __restrict__ lt,
             const int* __restrict__ tgt, float* __restrict__ out)
{
    __shared__ float4 shBins[NBINS];       // 32 KB: (inclT, inclS, binT, binS)
    __shared__ float  shA[NTHR], shB[NTHR];
    __shared__ float  shR[NTHR/32];

    const int tid  = threadIdx.x;
    const int bid  = blockIdx.x;
    const int lane = tid & 31;
    const int wid  = tid >> 5;

    // ============ Phase A: softmax + KD + L2 dots + histogram (blocks 0..39) ============
    if (bid < NAB){
        int gw = bid*(NTHR/32) + wid;          // always < 320
        int b = gw / KK, k = gw % KK;
        float invT = 1.0f / (float)(k+1);
        float av[4], bv[4];
        float amax = -FLT_MAX, bmax = -FLT_MAX;
        #pragma unroll
        for (int q=0;q<4;q++){
            int c = lane + 32*q;
            bool ok = c < CC;
            av[q] = ok ? ls[b*CC+c]*invT : -FLT_MAX;
            bv[q] = ok ? lt[b*CC+c]*invT : -FLT_MAX;
            amax = fmaxf(amax, av[q]);
            bmax = fmaxf(bmax, bv[q]);
        }
        #pragma unroll
        for (int o=16;o;o>>=1){
            amax = fmaxf(amax, __shfl_xor_sync(0xffffffffu, amax, o));
            bmax = fmaxf(bmax, __shfl_xor_sync(0xffffffffu, bmax, o));
        }
        float ea[4], eb[4], sumA = 0.f, sumB = 0.f;
        #pragma unroll
        for (int q=0;q<4;q++){
            int c = lane + 32*q;
            ea[q] = (c<CC) ? expf(av[q]-amax) : 0.f;
            eb[q] = (c<CC) ? expf(bv[q]-bmax) : 0.f;
            sumA += ea[q]; sumB += eb[q];
        }
        #pragma unroll
        for (int o=16;o;o>>=1){
            sumA += __shfl_xor_sync(0xffffffffu, sumA, o);
            sumB += __shfl_xor_sync(0xffffffffu, sumB, o);
        }
        float lA = logf(sumA), lB = logf(sumB);
        float rA = 1.f/sumA, rB = 1.f/sumB;
        int tg = (k==0) ? tgt[b] : -1;
        float kl=0.f, tt=0.f, ssv=0.f, tsv=0.f;
        #pragma unroll
        for (int q=0;q<4;q++){
            int c = lane + 32*q;
            if (c < CC){
                float lq = av[q]-amax-lA;
                float lp = bv[q]-bmax-lB;
                float sv = ea[q]*rA;
                float tv = eb[q]*rB;
                float dv = lp - lq;
                int idx = (b*CC + c)*KK + k;
                g_pack[idx] = make_float4(tv, sv, dv, 0.f);
                int i2 = (k*BB + b)*CC + c;
                g_tk[i2]=tv; g_sk[i2]=sv;
                int j = binOf(dv);
                atomicAdd(&g_hist2[j].x, tv);
                atomicAdd(&g_hist2[j].y, sv);
                kl  += tv*dv;
                tt  += tv*tv;
                ssv += sv*sv;
                tsv += tv*sv;
                if (c == tg) atomicAdd(&g_ce, (double)(-lq));
            }
        }
        #pragma unroll
        for (int o=16;o;o>>=1){
            kl  += __shfl_xor_sync(0xffffffffu, kl,  o);
            tt  += __shfl_xor_sync(0xffffffffu, tt,  o);
            ssv += __shfl_xor_sync(0xffffffffu, ssv, o);
            tsv += __shfl_xor_sync(0xffffffffu, tsv, o);
        }
        if (lane==0){
            atomicAdd(&g_kl[k], (double)kl);
            atomicAdd(&g_tt, (double)tt);
            atomicAdd(&g_ss, (double)ssv);
            atomicAdd(&g_ts, (double)tsv);
        }
        __threadfence();
        __syncthreads();
        if (tid==0) atomicAdd(&g_adone, 1u);
    }

    // ---- all blocks wait for Phase A (single counter at one L2 address) ----
    if (tid == 0){
        while (*(volatile unsigned*)&g_adone != NAB) { }
    }
    __threadfence();
    __syncthreads();

    if (bid < NLB){
        // ========== TEAM L: private smem scan of 2048 bins -> direct LDS lookups ==========
        // coalesced load of the raw histogram (16 KB) into smem
        const float4* hp = (const float4*)g_hist2;     // 1024 float4 = 2 bins each
        #pragma unroll
        for (int i = tid; i < NBINS/2; i += NTHR){     // 4 iterations
            float4 v = hp[i];
            shBins[2*i]   = make_float4(v.x, v.y, 0.f, 0.f);
            shBins[2*i+1] = make_float4(v.z, v.w, 0.f, 0.f);
        }
        __syncthreads();

        // per-thread serial prefix over its 8 bins
        float4 loc[8];
        float tAcc = 0.f, sAcc = 0.f;
        #pragma unroll
        for (int m=0;m<8;m++){
            loc[m] = shBins[tid*8+m];
            tAcc += loc[m].x; sAcc += loc[m].y;
        }
        shA[tid]=tAcc; shB[tid]=sAcc;
        __syncthreads();
        // block-wide inclusive scan over 256 partials
        #pragma unroll
        for (int off=1; off<NTHR; off<<=1){
            float vT=shA[tid], vS=shB[tid];
            float uT=0.f,uS=0.f;
            if (tid>=off){ uT=shA[tid-off]; uS=shB[tid-off]; }
            __syncthreads();
            shA[tid]=vT+uT; shB[tid]=vS+uS;
            __syncthreads();
        }
        float Ttot = shA[NTHR-1], Stot = shB[NTHR-1];
        float rT = tid? shA[tid-1]:0.f;
        float rS = tid? shB[tid-1]:0.f;
        // write back per-bin (inclusiveT, inclusiveS, binT, binS)
        #pragma unroll
        for (int m=0;m<8;m++){
            float bT = loc[m].x, bS = loc[m].y;
            rT += bT; rS += bS;
            shBins[tid*8+m] = make_float4(rT, rS, bT, bS);
        }
        __syncthreads();

        // --- L1: P_t(a) = suffix above bin(-d_a) + half of that bin (half-split approx) ---
        float contrib = 0.f;
        #pragma unroll
        for (int i=tid; i<NPB; i+=NTHR){               // 2 iterations
            float4 p = g_pack[bid*NPB + i];            // t=x, s=y, d=z
            int j = binOf(-p.z);
            float4 bp = shBins[j];
            float pt = Ttot - bp.x + 0.5f*bp.z;
            float ps = Stot - bp.y + 0.5f*bp.w;
            contrib += p.x*(2.f*pt - Ttot) - p.y*(2.f*ps - Stot);
        }
        float r2 = blockSum(contrib, shR);
        if (tid==0) atomicAdd(&g_l1, (double)r2);

        // --- cleanup for next replay: each L block zeroes its 32 bins ---
        if (tid < 32) g_hist2[bid*32 + tid] = make_float2(0.f, 0.f);
    } else {
        // =================== TEAM G: Gram sub losses, 4x4 tiles ===================
        const int NTG = KK*16*16;   // 1280 (BxB in 4x4 tiles)
        const int NTH = KK*25*25;   // 3125 (CxC in 4x4 tiles)
        int gid = (bid-NLB)*NTHR + tid;
        float val = 0.f;
        if (gid < NTG){
            int k  = gid >> 8;
            int r  = gid & 255;
            int i0 = (r >> 4) << 2;
            int j0 = (r & 15) << 2;
            const float* T = g_tk + k*BB*CC;
            const float* S = g_sk + k*BB*CC;
            float acc[16];
            #pragma unroll
            for (int q=0;q<16;q++) acc[q]=0.f;
            for (int c=0;c<CC;c++){
                float ti[4], tj[4], si[4], sj[4];
                #pragma unroll
                for (int d2=0;d2<4;d2++){
                    ti[d2]=T[(i0+d2)*CC+c]; tj[d2]=T[(j0+d2)*CC+c];
                    si[d2]=S[(i0+d2)*CC+c]; sj[d2]=S[(j0+d2)*CC+c];
                }
                #pragma unroll
                for (int di=0;di<4;di++)
                    #pragma unroll
                    for (int dj=0;dj<4;dj++)
                        acc[di*4+dj] += ti[di]*tj[dj] - si[di]*sj[dj];
            }
            #pragma unroll
            for (int q=0;q<16;q++) val += acc[q]*acc[q];
        } else if (gid < NTG + NTH){
            int u  = gid - NTG;
            int k  = u / 625;
            int r  = u - k*625;
            int i0 = (r / 25) * 4;
            int j0 = (r % 25) * 4;
            const float* T = g_tk + k*BB*CC;
            const float* S = g_sk + k*BB*CC;
            float acc[16];
            #pragma unroll
            for (int q=0;q<16;q++) acc[q]=0.f;
            for (int b2=0;b2<BB;b2++){
                float4 t4i = *(const float4*)(T + b2*CC + i0);
                float4 t4j = *(const float4*)(T + b2*CC + j0);
                float4 s4i = *(const float4*)(S + b2*CC + i0);
                float4 s4j = *(const float4*)(S + b2*CC + j0);
                float ti[4]={t4i.x,t4i.y,t4i.z,t4i.w};
                float tj[4]={t4j.x,t4j.y,t4j.z,t4j.w};
                float si[4]={s4i.x,s4i.y,s4i.z,s4i.w};
                float sj[4]={s4j.x,s4j.y,s4j.z,s4j.w};
                #pragma unroll
                for (int di=0;di<4;di++)
                    #pragma unroll
                    for (int dj=0;dj<4;dj++)
                        acc[di*4+dj] += ti[di]*tj[dj] - si[di]*sj[dj];
            }
            #pragma unroll
            for (int q=0;q<16;q++) val += acc[q]*acc[q];
        }
        float r2 = blockSum(val, shR);
        if (tid==0) atomicAdd(&g_sub, (double)r2);
    }

    // ============ Last block out does the final combine (no grid barrier) ============
    __threadfence();
    __syncthreads();
    if (tid == 0){
        if (atomicAdd(&g_done, 1u) == NBLK-1u){
            __threadfence();
            double ce = g_ce / (double)BB;
            double kd = 0.0;
            #pragma unroll
            for (int k=0;k<KK;k++){
                double T = (double)(k+1);
                kd += (g_kl[k] / (double)(BB*CC)) * (0.7*T*T) + ce * 0.3;
            }
            double tt=g_tt, ss2=g_ss, ts2=g_ts;
            double l2 = 0.00025*(tt*tt - 2.0*ts2*ts2 + ss2*ss2);
            out[0] = (float)(kd + 0.00025*g_l1 + l2 + g_sub);
            // reset state for next graph replay
            g_tt = 0.0; g_ss = 0.0; g_ts = 0.0;
            g_ce = 0.0; g_l1 = 0.0; g_sub = 0.0;
            #pragma unroll
            for (int k=0;k<KK;k++) g_kl[k] = 0.0;
            g_adone = 0u;
            g_done = 0u;
        }
    }
}

// ---------------- launch ----------------
extern "C" void kernel_launch(void* const* d_in, const int* in_sizes, int n_in,
                              void* d_out, int out_size){
    (void)in_sizes; (void)n_in; (void)out_size;
    const float* ls  = (const float*)d_in[0];  // logits_student [64,100]
    const float* lt  = (const float*)d_in[1];  // logits_teacher [64,100]
    const int*   tgt = (const int*)  d_in[2];  // target [64]
    float* out = (float*)d_out;

    fused_kernel<<<NBLK, NTHR>>>(ls, lt, tgt, out);
}

// round 10
// speedup vs baseline: 1.1167x; 1.1167x over previous
#include <cuda_runtime.h>
#include <math.h>
#include <float.h>

#define BB 64
#define CC 100
#define KK 5
#define NN (BB*CC*KK)      // 32000
#define NBINS 1024
#define NLB 64             // Team L blocks
#define NBLK 128
#define NTHR 256
#define NPB (NN/NLB)       // 500 elements per L block
#define NAB 40             // blocks active in Phase A (320 warp tasks / 8)
#define DMINF (-8.0f)
#define INVWF 64.0f        // NBINS / 16

// ---------------- device scratch (no allocs allowed) ----------------
__device__ float4 g_pack[NN];          // (t, s, d, 0)
__device__ float2 g_hist2[NBINS];      // (sumT, sumS) merged from block-private hists
__device__ float  g_tk[KK*BB*CC], g_sk[KK*BB*CC];   // [k][b][c]
__device__ double g_tt, g_ss, g_ts, g_kl[KK], g_ce, g_l1, g_sub;
__device__ unsigned g_adone;           // Phase-A completion counter
__device__ unsigned g_lout;            // Team-L exit counter (elects hist cleaner)
__device__ unsigned g_done;            // last-block-out counter

__device__ __forceinline__ int binOf(float x){
    int j = (int)floorf((x - DMINF) * INVWF);
    return min(max(j, 0), NBINS-1);    // clamp safe: extreme-|d| elements have tiny t*s
}

__device__ __forceinline__ float blockSum(float v, float* shR){
    int lane = threadIdx.x & 31, w = threadIdx.x >> 5;
    #pragma unroll
    for (int o=16;o;o>>=1) v += __shfl_down_sync(0xffffffffu, v, o);
    if (lane==0) shR[w] = v;
    __syncthreads();
    float r = 0.f;
    if (threadIdx.x==0){
        #pragma unroll
        for (int i=0;i<NTHR/32;i++) r += shR[i];
    }
    __syncthreads();
    return r;   // valid on tid 0 only
}

__global__ void __launch_bounds__(NTHR)
fused_kernel(const float* __restrict__ ls, const float* __restrict__ lt,
             const int* __restrict__ tgt, float* __restrict__ out)
{
    __shared__ float4 shT[NBINS];          // 16 KB: L table / (first 8 KB) A private hist
    __shared__ float  shA[NTHR], shB[NTHR];
    __shared__ float  shR[NTHR/32];
    __shared__ float  shKL[KK], shTT, shSS, shTS;
    __shared__ int    shLast;

    const int tid  = threadIdx.x;
    const int bid  = blockIdx.x;
    const int lane = tid & 31;
    const int wid  = tid >> 5;

    // ============ Phase A: softmax + KD + L2 dots + PRIVATE smem histogram ============
    if (bid < NAB){
        float2* shH = (float2*)shT;        // 1024-bin private histogram (8 KB)
        #pragma unroll
        for (int i=tid; i<NBINS; i+=NTHR) shH[i] = make_float2(0.f, 0.f);
        if (tid < KK) shKL[tid] = 0.f;
        if (tid == KK)   shTT = 0.f;
        if (tid == KK+1) shSS = 0.f;
        if (tid == KK+2) shTS = 0.f;
        __syncthreads();

        int gw = bid*(NTHR/32) + wid;      // always < 320
        int b = gw / KK, k = gw % KK;
        float invT = 1.0f / (float)(k+1);
        float av[4], bv[4];
        float amax = -FLT_MAX, bmax = -FLT_MAX;
        #pragma unroll
        for (int q=0;q<4;q++){
            int c = lane + 32*q;
            bool ok = c < CC;
            av[q] = ok ? ls[b*CC+c]*invT : -FLT_MAX;
            bv[q] = ok ? lt[b*CC+c]*invT : -FLT_MAX;
            amax = fmaxf(amax, av[q]);
            bmax = fmaxf(bmax, bv[q]);
        }
        #pragma unroll
        for (int o=16;o;o>>=1){
            amax = fmaxf(amax, __shfl_xor_sync(0xffffffffu, amax, o));
            bmax = fmaxf(bmax, __shfl_xor_sync(0xffffffffu, bmax, o));
        }
        float ea[4], eb[4], sumA = 0.f, sumB = 0.f;
        #pragma unroll
        for (int q=0;q<4;q++){
            int c = lane + 32*q;
            ea[q] = (c<CC) ? expf(av[q]-amax) : 0.f;
            eb[q] = (c<CC) ? expf(bv[q]-bmax) : 0.f;
            sumA += ea[q]; sumB += eb[q];
        }
        #pragma unroll
        for (int o=16;o;o>>=1){
            sumA += __shfl_xor_sync(0xffffffffu, sumA, o);
            sumB += __shfl_xor_sync(0xffffffffu, sumB, o);
        }
        float lA = logf(sumA), lB = logf(sumB);
        float rA = 1.f/sumA, rB = 1.f/sumB;
        int tg = (k==0) ? tgt[b] : -1;
        float kl=0.f, tt=0.f, ssv=0.f, tsv=0.f;
        #pragma unroll
        for (int q=0;q<4;q++){
            int c = lane + 32*q;
            if (c < CC){
                float lq = av[q]-amax-lA;
                float lp = bv[q]-bmax-lB;
                float sv = ea[q]*rA;
                float tv = eb[q]*rB;
                float dv = lp - lq;
                int idx = (b*CC + c)*KK + k;
                g_pack[idx] = make_float4(tv, sv, dv, 0.f);
                int i2 = (k*BB + b)*CC + c;
                g_tk[i2]=tv; g_sk[i2]=sv;
                int j = binOf(dv);
                atomicAdd(&shH[j].x, tv);      // smem atomics: no L2 serialization
                atomicAdd(&shH[j].y, sv);
                kl  += tv*dv;
                tt  += tv*tv;
                ssv += sv*sv;
                tsv += tv*sv;
                if (c == tg) atomicAdd(&g_ce, (double)(-lq));
            }
        }
        #pragma unroll
        for (int o=16;o;o>>=1){
            kl  += __shfl_xor_sync(0xffffffffu, kl,  o);
            tt  += __shfl_xor_sync(0xffffffffu, tt,  o);
            ssv += __shfl_xor_sync(0xffffffffu, ssv, o);
            tsv += __shfl_xor_sync(0xffffffffu, tsv, o);
        }
        if (lane==0){
            atomicAdd(&shKL[k], kl);
            atomicAdd(&shTT, tt);
            atomicAdd(&shSS, ssv);
            atomicAdd(&shTS, tsv);
        }
        __syncthreads();

        // merge private hist -> global (skip empty bins; contention <= 40/address)
        #pragma unroll
        for (int i=tid; i<NBINS; i+=NTHR){
            float2 h = shH[i];
            if (h.x != 0.f || h.y != 0.f){
                atomicAdd(&g_hist2[i].x, h.x);
                atomicAdd(&g_hist2[i].y, h.y);
            }
        }
        // per-block scalar merge: 40 atomics per address instead of 320
        if (tid < KK)     atomicAdd(&g_kl[tid], (double)shKL[tid]);
        if (tid == KK)    atomicAdd(&g_tt, (double)shTT);
        if (tid == KK+1)  atomicAdd(&g_ss, (double)shSS);
        if (tid == KK+2)  atomicAdd(&g_ts, (double)shTS);
        __threadfence();
        __syncthreads();
        if (tid==0) atomicAdd(&g_adone, 1u);
    }

    // ---- all blocks wait for Phase A (single counter, pure spin by tid 0) ----
    if (tid == 0){
        while (*(volatile unsigned*)&g_adone != NAB) { }
    }
    __threadfence();
    __syncthreads();

    if (bid < NLB){
        // ========== TEAM L: private smem scan of 1024 bins -> direct LDS lookups ==========
        // coalesced 8 KB load: 4 bins per thread
        float4 A0 = ((const float4*)g_hist2)[2*tid];     // bins 4t, 4t+1
        float4 A1 = ((const float4*)g_hist2)[2*tid+1];   // bins 4t+2, 4t+3
        float bt[4] = {A0.x, A0.z, A1.x, A1.z};
        float bs[4] = {A0.y, A0.w, A1.y, A1.w};
        float tAcc = bt[0]+bt[1]+bt[2]+bt[3];
        float sAcc = bs[0]+bs[1]+bs[2]+bs[3];
        shA[tid]=tAcc; shB[tid]=sAcc;
        __syncthreads();
        #pragma unroll
        for (int off=1; off<NTHR; off<<=1){
            float vT=shA[tid], vS=shB[tid];
            float uT=0.f,uS=0.f;
            if (tid>=off){ uT=shA[tid-off]; uS=shB[tid-off]; }
            __syncthreads();
            shA[tid]=vT+uT; shB[tid]=vS+uS;
            __syncthreads();
        }
        float Ttot = shA[NTHR-1], Stot = shB[NTHR-1];
        float rT = tid? shA[tid-1]:0.f;
        float rS = tid? shB[tid-1]:0.f;
        #pragma unroll
        for (int m=0;m<4;m++){
            rT += bt[m]; rS += bs[m];
            shT[4*tid+m] = make_float4(rT, rS, bt[m], bs[m]);  // (inclT, inclS, binT, binS)
        }
        __syncthreads();

        // --- L1: P_t(a) = suffix above bin(-d_a) + half of that bin (half-split) ---
        float contrib = 0.f;
        #pragma unroll
        for (int i=tid; i<NPB; i+=NTHR){               // 2 iterations
            float4 p = g_pack[bid*NPB + i];            // t=x, s=y, d=z
            int j = binOf(-p.z);
            float4 bp = shT[j];
            float pt = Ttot - bp.x + 0.5f*bp.z;
            float ps = Stot - bp.y + 0.5f*bp.w;
            contrib += p.x*(2.f*pt - Ttot) - p.y*(2.f*ps - Stot);
        }
        float r2 = blockSum(contrib, shR);
        if (tid==0) atomicAdd(&g_l1, (double)r2);

        // --- last L block out zeroes the global hist (all readers finished) ---
        __syncthreads();
        if (tid==0) shLast = (atomicAdd(&g_lout, 1u) == NLB-1u) ? 1 : 0;
        __syncthreads();
        if (shLast){
            #pragma unroll
            for (int i=tid; i<NBINS; i+=NTHR) g_hist2[i] = make_float2(0.f, 0.f);
            if (tid==0) g_lout = 0u;
        }
    } else {
        // =================== TEAM G: Gram sub losses, 4x4 tiles ===================
        const int NTG = KK*16*16;   // 1280 (BxB in 4x4 tiles)
        const int NTH = KK*25*25;   // 3125 (CxC in 4x4 tiles)
        int gid = (bid-NLB)*NTHR + tid;
        float val = 0.f;
        if (gid < NTG){
            int k  = gid >> 8;
            int r  = gid & 255;
            int i0 = (r >> 4) << 2;
            int j0 = (r & 15) << 2;
            const float* T = g_tk + k*BB*CC;
            const float* S = g_sk + k*BB*CC;
            float acc[16];
            #pragma unroll
            for (int q=0;q<16;q++) acc[q]=0.f;
            for (int c=0;c<CC;c++){
                float ti[4], tj[4], si[4], sj[4];
                #pragma unroll
                for (int d2=0;d2<4;d2++){
                    ti[d2]=T[(i0+d2)*CC+c]; tj[d2]=T[(j0+d2)*CC+c];
                    si[d2]=S[(i0+d2)*CC+c]; sj[d2]=S[(j0+d2)*CC+c];
                }
                #pragma unroll
                for (int di=0;di<4;di++)
                    #pragma unroll
                    for (int dj=0;dj<4;dj++)
                        acc[di*4+dj] += ti[di]*tj[dj] - si[di]*sj[dj];
            }
            #pragma unroll
            for (int q=0;q<16;q++) val += acc[q]*acc[q];
        } else if (gid < NTG + NTH){
            int u  = gid - NTG;
            int k  = u / 625;
            int r  = u - k*625;
            int i0 = (r / 25) * 4;
            int j0 = (r % 25) * 4;
            const float* T = g_tk + k*BB*CC;
            const float* S = g_sk + k*BB*CC;
            float acc[16];
            #pragma unroll
            for (int q=0;q<16;q++) acc[q]=0.f;
            for (int b2=0;b2<BB;b2++){
                float4 t4i = *(const float4*)(T + b2*CC + i0);
                float4 t4j = *(const float4*)(T + b2*CC + j0);
                float4 s4i = *(const float4*)(S + b2*CC + i0);
                float4 s4j = *(const float4*)(S + b2*CC + j0);
                float ti[4]={t4i.x,t4i.y,t4i.z,t4i.w};
                float tj[4]={t4j.x,t4j.y,t4j.z,t4j.w};
                float si[4]={s4i.x,s4i.y,s4i.z,s4i.w};
                float sj[4]={s4j.x,s4j.y,s4j.z,s4j.w};
                #pragma unroll
                for (int di=0;di<4;di++)
                    #pragma unroll
                    for (int dj=0;dj<4;dj++)
                        acc[di*4+dj] += ti[di]*tj[dj] - si[di]*sj[dj];
            }
            #pragma unroll
            for (int q=0;q<16;q++) val += acc[q]*acc[q];
        }
        float r2 = blockSum(val, shR);
        if (tid==0) atomicAdd(&g_sub, (double)r2);
    }

    // ============ Last block out does the final combine (no grid barrier) ============
    __threadfence();
    __syncthreads();
    if (tid == 0){
        if (atomicAdd(&g_done, 1u) == NBLK-1u){
            __threadfence();
            double ce = g_ce / (double)BB;
            double kd = 0.0;
            #pragma unroll
            for (int k=0;k<KK;k++){
                double T = (double)(k+1);
                kd += (g_kl[k] / (double)(BB*CC)) * (0.7*T*T) + ce * 0.3;
            }
            double tt=g_tt, ss2=g_ss, ts2=g_ts;
            double l2 = 0.00025*(tt*tt - 2.0*ts2*ts2 + ss2*ss2);
            out[0] = (float)(kd + 0.00025*g_l1 + l2 + g_sub);
            // reset state for next graph replay
            g_tt = 0.0; g_ss = 0.0; g_ts = 0.0;
            g_ce = 0.0; g_l1 = 0.0; g_sub = 0.0;
            #pragma unroll
            for (int k=0;k<KK;k++) g_kl[k] = 0.0;
            g_adone = 0u;
            g_done = 0u;
        }
    }
}

// ---------------- launch ----------------
extern "C" void kernel_launch(void* const* d_in, const int* in_sizes, int n_in,
                              void* d_out, int out_size){
    (void)in_sizes; (void)n_in; (void)out_size;
    const float* ls  = (const float*)d_in[0];  // logits_student [64,100]
    const float* lt  = (const float*)d_in[1];  // logits_teacher [64,100]
    const int*   tgt = (const int*)  d_in[2];  // target [64]
    float* out = (float*)d_out;

    fused_kernel<<<NBLK, NTHR>>>(ls, lt, tgt, out);
}

// round 11
// speedup vs baseline: 1.6613x; 1.4876x over previous
#include <cuda_runtime.h>
#include <math.h>
#include <float.h>

#define BB 64
#define CC 100
#define KK 5
#define NN (BB*CC*KK)      // 32000
#define NBINS 1024
#define NAB 40             // A+L1 blocks (320 warp tasks / 8)
#define NGB 64             // Gram blocks
#define NBLK (NAB+NGB)     // 104
#define NTHR 256
#define DMINF (-8.0f)
#define INVWF 64.0f        // NBINS / 16

// ---------------- device scratch (no allocs allowed) ----------------
__device__ float2 g_hist2[NBINS];      // (sumT, sumS) merged from block-private hists
__device__ float  g_tk[KK*BB*CC], g_sk[KK*BB*CC];   // [k][b][c]
__device__ double g_tt, g_ss, g_ts, g_kl[KK], g_ce, g_l1, g_sub;
__device__ unsigned g_adone;           // Phase-A completion counter
__device__ unsigned g_done;            // last-block-out counter

__device__ __forceinline__ int binOf(float x){
    int j = (int)floorf((x - DMINF) * INVWF);
    return min(max(j, 0), NBINS-1);    // clamp safe: extreme-|d| elements have tiny t*s
}

__device__ __forceinline__ float blockSum(float v, float* shR){
    int lane = threadIdx.x & 31, w = threadIdx.x >> 5;
    #pragma unroll
    for (int o=16;o;o>>=1) v += __shfl_down_sync(0xffffffffu, v, o);
    if (lane==0) shR[w] = v;
    __syncthreads();
    float r = 0.f;
    if (threadIdx.x==0){
        #pragma unroll
        for (int i=0;i<NTHR/32;i++) r += shR[i];
    }
    __syncthreads();
    return r;   // valid on tid 0 only
}

__global__ void __launch_bounds__(NTHR)
fused_kernel(const float* __restrict__ ls, const float* __restrict__ lt,
             const int* __restrict__ tgt, float* __restrict__ out)
{
    __shared__ float4 shT[NBINS];          // 16 KB: scan table; first 8 KB doubles as private hist
    __shared__ float  shA[NTHR], shB[NTHR];
    __shared__ float  shR[NTHR/32];
    __shared__ float  shKL[KK], shTT, shSS, shTS;
    __shared__ int    shLast;

    const int tid  = threadIdx.x;
    const int bid  = blockIdx.x;
    const int lane = tid & 31;
    const int wid  = tid >> 5;

    if (bid < NAB){
        // ============ Phase A: softmax + KD + L2 dots + private hist (t,s,d stay in regs) ============
        float2* shH = (float2*)shT;        // 1024-bin private histogram (8 KB)
        #pragma unroll
        for (int i=tid; i<NBINS; i+=NTHR) shH[i] = make_float2(0.f, 0.f);
        if (tid < KK) shKL[tid] = 0.f;
        if (tid == KK)   shTT = 0.f;
        if (tid == KK+1) shSS = 0.f;
        if (tid == KK+2) shTS = 0.f;
        __syncthreads();

        int gw = bid*(NTHR/32) + wid;      // always < 320
        int b = gw / KK, k = gw % KK;
        float invT = 1.0f / (float)(k+1);
        float av[4], bv[4];
        float amax = -FLT_MAX, bmax = -FLT_MAX;
        #pragma unroll
        for (int q=0;q<4;q++){
            int c = lane + 32*q;
            bool ok = c < CC;
            av[q] = ok ? ls[b*CC+c]*invT : -FLT_MAX;
            bv[q] = ok ? lt[b*CC+c]*invT : -FLT_MAX;
            amax = fmaxf(amax, av[q]);
            bmax = fmaxf(bmax, bv[q]);
        }
        #pragma unroll
        for (int o=16;o;o>>=1){
            amax = fmaxf(amax, __shfl_xor_sync(0xffffffffu, amax, o));
            bmax = fmaxf(bmax, __shfl_xor_sync(0xffffffffu, bmax, o));
        }
        float ea[4], eb[4], sumA = 0.f, sumB = 0.f;
        #pragma unroll
        for (int q=0;q<4;q++){
            int c = lane + 32*q;
            ea[q] = (c<CC) ? expf(av[q]-amax) : 0.f;
            eb[q] = (c<CC) ? expf(bv[q]-bmax) : 0.f;
            sumA += ea[q]; sumB += eb[q];
        }
        #pragma unroll
        for (int o=16;o;o>>=1){
            sumA += __shfl_xor_sync(0xffffffffu, sumA, o);
            sumB += __shfl_xor_sync(0xffffffffu, sumB, o);
        }
        float lA = logf(sumA), lB = logf(sumB);
        float rA = 1.f/sumA, rB = 1.f/sumB;
        int tg = (k==0) ? tgt[b] : -1;
        float tv[4], sv[4], dv[4];         // elements stay resident in registers
        float kl=0.f, tt=0.f, ssv=0.f, tsv=0.f;
        #pragma unroll
        for (int q=0;q<4;q++){
            int c = lane + 32*q;
            tv[q]=0.f; sv[q]=0.f; dv[q]=0.f;
            if (c < CC){
                float lq = av[q]-amax-lA;
                float lp = bv[q]-bmax-lB;
                sv[q] = ea[q]*rA;
                tv[q] = eb[q]*rB;
                dv[q] = lp - lq;
                int i2 = (k*BB + b)*CC + c;
                g_tk[i2]=tv[q]; g_sk[i2]=sv[q];
                int j = binOf(dv[q]);
                atomicAdd(&shH[j].x, tv[q]);
                atomicAdd(&shH[j].y, sv[q]);
                kl  += tv[q]*dv[q];
                tt  += tv[q]*tv[q];
                ssv += sv[q]*sv[q];
                tsv += tv[q]*sv[q];
                if (c == tg) atomicAdd(&g_ce, (double)(-lq));
            }
        }
        #pragma unroll
        for (int o=16;o;o>>=1){
            kl  += __shfl_xor_sync(0xffffffffu, kl,  o);
            tt  += __shfl_xor_sync(0xffffffffu, tt,  o);
            ssv += __shfl_xor_sync(0xffffffffu, ssv, o);
            tsv += __shfl_xor_sync(0xffffffffu, tsv, o);
        }
        if (lane==0){
            atomicAdd(&shKL[k], kl);
            atomicAdd(&shTT, tt);
            atomicAdd(&shSS, ssv);
            atomicAdd(&shTS, tsv);
        }
        __syncthreads();

        // merge private hist -> global (skip empty bins; contention <= 40/address)
        #pragma unroll
        for (int i=tid; i<NBINS; i+=NTHR){
            float2 h = shH[i];
            if (h.x != 0.f || h.y != 0.f){
                atomicAdd(&g_hist2[i].x, h.x);
                atomicAdd(&g_hist2[i].y, h.y);
            }
        }
        if (tid < KK)     atomicAdd(&g_kl[tid], (double)shKL[tid]);
        if (tid == KK)    atomicAdd(&g_tt, (double)shTT);
        if (tid == KK+1)  atomicAdd(&g_ss, (double)shSS);
        if (tid == KK+2)  atomicAdd(&g_ts, (double)shTS);
        __threadfence();
        __syncthreads();
        if (tid==0) atomicAdd(&g_adone, 1u);

        // ---- wait for ALL A blocks (single counter) ----
        if (tid == 0){
            while (*(volatile unsigned*)&g_adone != NAB) { }
        }
        __threadfence();
        __syncthreads();

        // ---- build full scan table in own smem (4 bins/thread) ----
        float4 A0 = ((const float4*)g_hist2)[2*tid];     // bins 4t, 4t+1
        float4 A1 = ((const float4*)g_hist2)[2*tid+1];   // bins 4t+2, 4t+3
        float bt[4] = {A0.x, A0.z, A1.x, A1.z};
        float bs[4] = {A0.y, A0.w, A1.y, A1.w};
        shA[tid] = bt[0]+bt[1]+bt[2]+bt[3];
        shB[tid] = bs[0]+bs[1]+bs[2]+bs[3];
        __syncthreads();
        #pragma unroll
        for (int off=1; off<NTHR; off<<=1){
            float vT=shA[tid], vS=shB[tid];
            float uT=0.f,uS=0.f;
            if (tid>=off){ uT=shA[tid-off]; uS=shB[tid-off]; }
            __syncthreads();
            shA[tid]=vT+uT; shB[tid]=vS+uS;
            __syncthreads();
        }
        float Ttot = shA[NTHR-1], Stot = shB[NTHR-1];
        float rT = tid? shA[tid-1]:0.f;
        float rS = tid? shB[tid-1]:0.f;
        #pragma unroll
        for (int m=0;m<4;m++){
            rT += bt[m]; rS += bs[m];
            shT[4*tid+m] = make_float4(rT, rS, bt[m], bs[m]);  // (inclT, inclS, binT, binS)
        }
        __syncthreads();

        // ---- L1 from registers: P_t = suffix above bin(-d) + half of that bin ----
        float contrib = 0.f;
        #pragma unroll
        for (int q=0;q<4;q++){
            int c = lane + 32*q;
            if (c < CC){
                int j = binOf(-dv[q]);
                float4 bp = shT[j];
                float pt = Ttot - bp.x + 0.5f*bp.z;
                float ps = Stot - bp.y + 0.5f*bp.w;
                contrib += tv[q]*(2.f*pt - Ttot) - sv[q]*(2.f*ps - Stot);
            }
        }
        float r2 = blockSum(contrib, shR);
        if (tid==0) atomicAdd(&g_l1, (double)r2);
    } else {
        // =================== Gram blocks: wait for A, then 4x4 tiles ===================
        if (tid == 0){
            while (*(volatile unsigned*)&g_adone != NAB) { }
        }
        __threadfence();
        __syncthreads();

        const int NTG = KK*16*16;   // 1280 (BxB in 4x4 tiles)
        const int NTH = KK*25*25;   // 3125 (CxC in 4x4 tiles)
        int gid = (bid-NAB)*NTHR + tid;
        float val = 0.f;
        if (gid < NTG){
            int k  = gid >> 8;
            int r  = gid & 255;
            int i0 = (r >> 4) << 2;
            int j0 = (r & 15) << 2;
            const float* T = g_tk + k*BB*CC;
            const float* S = g_sk + k*BB*CC;
            float acc[16];
            #pragma unroll
            for (int q=0;q<16;q++) acc[q]=0.f;
            for (int c4=0;c4<CC;c4+=4){
                float4 Ti[4], Tj[4], Si[4], Sj[4];
                #pragma unroll
                for (int d2=0;d2<4;d2++){
                    Ti[d2]=*(const float4*)(T+(i0+d2)*CC+c4);
                    Tj[d2]=*(const float4*)(T+(j0+d2)*CC+c4);
                    Si[d2]=*(const float4*)(S+(i0+d2)*CC+c4);
                    Sj[d2]=*(const float4*)(S+(j0+d2)*CC+c4);
                }
                #pragma unroll
                for (int di=0;di<4;di++)
                    #pragma unroll
                    for (int dj=0;dj<4;dj++)
                        acc[di*4+dj] += Ti[di].x*Tj[dj].x - Si[di].x*Sj[dj].x
                                      + Ti[di].y*Tj[dj].y - Si[di].y*Sj[dj].y
                                      + Ti[di].z*Tj[dj].z - Si[di].z*Sj[dj].z
                                      + Ti[di].w*Tj[dj].w - Si[di].w*Sj[dj].w;
            }
            #pragma unroll
            for (int q=0;q<16;q++) val += acc[q]*acc[q];
        } else if (gid < NTG + NTH){
            int u  = gid - NTG;
            int k  = u / 625;
            int r  = u - k*625;
            int i0 = (r / 25) * 4;
            int j0 = (r % 25) * 4;
            const float* T = g_tk + k*BB*CC;
            const float* S = g_sk + k*BB*CC;
            float acc[16];
            #pragma unroll
            for (int q=0;q<16;q++) acc[q]=0.f;
            for (int b2=0;b2<BB;b2++){
                float4 t4i = *(const float4*)(T + b2*CC + i0);
                float4 t4j = *(const float4*)(T + b2*CC + j0);
                float4 s4i = *(const float4*)(S + b2*CC + i0);
                float4 s4j = *(const float4*)(S + b2*CC + j0);
                float ti[4]={t4i.x,t4i.y,t4i.z,t4i.w};
                float tj[4]={t4j.x,t4j.y,t4j.z,t4j.w};
                float si[4]={s4i.x,s4i.y,s4i.z,s4i.w};
                float sj[4]={s4j.x,s4j.y,s4j.z,s4j.w};
                #pragma unroll
                for (int di=0;di<4;di++)
                    #pragma unroll
                    for (int dj=0;dj<4;dj++)
                        acc[di*4+dj] += ti[di]*tj[dj] - si[di]*sj[dj];
            }
            #pragma unroll
            for (int q=0;q<16;q++) val += acc[q]*acc[q];
        }
        float r2 = blockSum(val, shR);
        if (tid==0) atomicAdd(&g_sub, (double)r2);
    }

    // ============ Last block out: final combine + full state reset ============
    __threadfence();
    __syncthreads();
    if (tid==0) shLast = (atomicAdd(&g_done, 1u) == NBLK-1u) ? 1 : 0;
    __syncthreads();
    if (shLast){
        if (tid == 0){
            __threadfence();
            double ce = g_ce / (double)BB;
            double kd = 0.0;
            #pragma unroll
            for (int k=0;k<KK;k++){
                double T = (double)(k+1);
                kd += (g_kl[k] / (double)(BB*CC)) * (0.7*T*T) + ce * 0.3;
            }
            double tt=g_tt, ss2=g_ss, ts2=g_ts;
            double l2 = 0.00025*(tt*tt - 2.0*ts2*ts2 + ss2*ss2);
            out[0] = (float)(kd + 0.00025*g_l1 + l2 + g_sub);
            // reset scalars for next graph replay
            g_tt = 0.0; g_ss = 0.0; g_ts = 0.0;
            g_ce = 0.0; g_l1 = 0.0; g_sub = 0.0;
            #pragma unroll
            for (int k=0;k<KK;k++) g_kl[k] = 0.0;
            g_adone = 0u;
            g_done = 0u;
        }
        // whole last block zeroes the histogram (all readers finished before g_done)
        #pragma unroll
        for (int i=tid; i<NBINS; i+=NTHR) g_hist2[i] = make_float2(0.f, 0.f);
    }
}

// ---------------- launch ----------------
extern "C" void kernel_launch(void* const* d_in, const int* in_sizes, int n_in,
                              void* d_out, int out_size){
    (void)in_sizes; (void)n_in; (void)out_size;
    const float* ls  = (const float*)d_in[0];  // logits_student [64,100]
    const float* lt  = (const float*)d_in[1];  // logits_teacher [64,100]
    const int*   tgt = (const int*)  d_in[2];  // target [64]
    float* out = (float*)d_out;

    fused_kernel<<<NBLK, NTHR>>>(ls, lt, tgt, out);
}

// round 12
// speedup vs baseline: 1.6969x; 1.0214x over previous
#include <cuda_runtime.h>
#include <math.h>
#include <float.h>

#define BB 64
#define CC 100
#define KK 5
#define NN (BB*CC*KK)      // 32000
#define NBINS 1024
#define NAB 40             // Phase-A blocks (320 warp tasks / 8)
#define NGB 18             // Gram blocks (4405 work items / 256)
#define NBLK (NAB+NGB)     // 58
#define NTHR 256
#define DMINF (-8.0f)
#define INVWF 64.0f        // NBINS / 16; symmetric range => binOf(-d) == 1023 - binOf(d)

// ---------------- device scratch (no allocs allowed) ----------------
__device__ float2 g_hist2[NBINS];      // (sumT, sumS) merged from block-private hists
__device__ float  g_tk[KK*BB*CC], g_sk[KK*BB*CC];   // [k][b][c]
__device__ double g_tt, g_ss, g_ts, g_kl[KK], g_ce, g_sub;
__device__ unsigned g_tkdone;          // tk/sk stores complete
__device__ unsigned g_adone;           // full Phase-A complete (hist + scalars merged)
__device__ unsigned g_gdone;           // Gram blocks complete

__device__ __forceinline__ int binOf(float x){
    int j = (int)floorf((x - DMINF) * INVWF);
    return min(max(j, 0), NBINS-1);    // clamp safe: mirror-consistent at both ends
}

__device__ __forceinline__ float blockSum(float v, float* shR){
    int lane = threadIdx.x & 31, w = threadIdx.x >> 5;
    #pragma unroll
    for (int o=16;o;o>>=1) v += __shfl_down_sync(0xffffffffu, v, o);
    if (lane==0) shR[w] = v;
    __syncthreads();
    float r = 0.f;
    if (threadIdx.x==0){
        #pragma unroll
        for (int i=0;i<NTHR/32;i++) r += shR[i];
    }
    __syncthreads();
    return r;   // valid on tid 0 only
}

__global__ void __launch_bounds__(NTHR)
fused_kernel(const float* __restrict__ ls, const float* __restrict__ lt,
             const int* __restrict__ tgt, float* __restrict__ out)
{
    __shared__ float4 shT[NBINS];          // 16 KB: block0 scan table; low 8 KB = A private hist
    __shared__ float  shA[NTHR], shB[NTHR];
    __shared__ float  shR[NTHR/32];
    __shared__ float  shKL[KK], shTT, shSS, shTS;

    const int tid  = threadIdx.x;
    const int bid  = blockIdx.x;
    const int lane = tid & 31;
    const int wid  = tid >> 5;

    if (bid < NAB){
        // ============ Phase A: softmax + KD + L2 dots + private smem hist ============
        float2* shH = (float2*)shT;        // 1024-bin private histogram (8 KB)
        #pragma unroll
        for (int i=tid; i<NBINS; i+=NTHR) shH[i] = make_float2(0.f, 0.f);
        if (tid < KK) shKL[tid] = 0.f;
        if (tid == KK)   shTT = 0.f;
        if (tid == KK+1) shSS = 0.f;
        if (tid == KK+2) shTS = 0.f;
        __syncthreads();

        int gw = bid*(NTHR/32) + wid;      // always < 320
        int b = gw / KK, k = gw % KK;
        float invT = 1.0f / (float)(k+1);
        float av[4], bv[4];
        float amax = -FLT_MAX, bmax = -FLT_MAX;
        #pragma unroll
        for (int q=0;q<4;q++){
            int c = lane + 32*q;
            bool ok = c < CC;
            av[q] = ok ? ls[b*CC+c]*invT : -FLT_MAX;
            bv[q] = ok ? lt[b*CC+c]*invT : -FLT_MAX;
            amax = fmaxf(amax, av[q]);
            bmax = fmaxf(bmax, bv[q]);
        }
        #pragma unroll
        for (int o=16;o;o>>=1){
            amax = fmaxf(amax, __shfl_xor_sync(0xffffffffu, amax, o));
            bmax = fmaxf(bmax, __shfl_xor_sync(0xffffffffu, bmax, o));
        }
        float ea[4], eb[4], sumA = 0.f, sumB = 0.f;
        #pragma unroll
        for (int q=0;q<4;q++){
            int c = lane + 32*q;
            ea[q] = (c<CC) ? expf(av[q]-amax) : 0.f;
            eb[q] = (c<CC) ? expf(bv[q]-bmax) : 0.f;
            sumA += ea[q]; sumB += eb[q];
        }
        #pragma unroll
        for (int o=16;o;o>>=1){
            sumA += __shfl_xor_sync(0xffffffffu, sumA, o);
            sumB += __shfl_xor_sync(0xffffffffu, sumB, o);
        }
        float lA = logf(sumA), lB = logf(sumB);
        float rA = 1.f/sumA, rB = 1.f/sumB;
        int tg = (k==0) ? tgt[b] : -1;
        float kl=0.f, tt=0.f, ssv=0.f, tsv=0.f;
        #pragma unroll
        for (int q=0;q<4;q++){
            int c = lane + 32*q;
            if (c < CC){
                float lq = av[q]-amax-lA;
                float lp = bv[q]-bmax-lB;
                float sv = ea[q]*rA;
                float tv = eb[q]*rB;
                float dv = lp - lq;
                int i2 = (k*BB + b)*CC + c;
                g_tk[i2]=tv; g_sk[i2]=sv;
                int j = binOf(dv);
                atomicAdd(&shH[j].x, tv);
                atomicAdd(&shH[j].y, sv);
                kl  += tv*dv;
                tt  += tv*tv;
                ssv += sv*sv;
                tsv += tv*sv;
                if (c == tg) atomicAdd(&g_ce, (double)(-lq));
            }
        }
        #pragma unroll
        for (int o=16;o;o>>=1){
            kl  += __shfl_xor_sync(0xffffffffu, kl,  o);
            tt  += __shfl_xor_sync(0xffffffffu, tt,  o);
            ssv += __shfl_xor_sync(0xffffffffu, ssv, o);
            tsv += __shfl_xor_sync(0xffffffffu, tsv, o);
        }
        if (lane==0){
            atomicAdd(&shKL[k], kl);
            atomicAdd(&shTT, tt);
            atomicAdd(&shSS, ssv);
            atomicAdd(&shTS, tsv);
        }
        __threadfence();                    // tk/sk stores visible
        __syncthreads();
        if (tid==0) atomicAdd(&g_tkdone, 1u);   // early release for Gram blocks

        // merge private hist -> global (skip empty bins; contention <= 40/address)
        #pragma unroll
        for (int i=tid; i<NBINS; i+=NTHR){
            float2 h = shH[i];
            if (h.x != 0.f || h.y != 0.f){
                atomicAdd(&g_hist2[i].x, h.x);
                atomicAdd(&g_hist2[i].y, h.y);
            }
        }
        if (tid < KK)     atomicAdd(&g_kl[tid], (double)shKL[tid]);
        if (tid == KK)    atomicAdd(&g_tt, (double)shTT);
        if (tid == KK+1)  atomicAdd(&g_ss, (double)shSS);
        if (tid == KK+2)  atomicAdd(&g_ts, (double)shTS);
        __threadfence();
        __syncthreads();
        if (tid==0) atomicAdd(&g_adone, 1u);

        if (bid == 0){
            // ============ Block 0: bin-space L1 + final combine ============
            if (tid == 0){
                while (*(volatile unsigned*)&g_adone != NAB) { }
            }
            __threadfence();
            __syncthreads();

            // load merged hist (4 bins/thread), scan, build table
            float4 A0 = ((const float4*)g_hist2)[2*tid];     // bins 4t, 4t+1
            float4 A1 = ((const float4*)g_hist2)[2*tid+1];   // bins 4t+2, 4t+3
            float bt[4] = {A0.x, A0.z, A1.x, A1.z};
            float bs[4] = {A0.y, A0.w, A1.y, A1.w};
            shA[tid] = bt[0]+bt[1]+bt[2]+bt[3];
            shB[tid] = bs[0]+bs[1]+bs[2]+bs[3];
            __syncthreads();
            #pragma unroll
            for (int off=1; off<NTHR; off<<=1){
                float vT=shA[tid], vS=shB[tid];
                float uT=0.f,uS=0.f;
                if (tid>=off){ uT=shA[tid-off]; uS=shB[tid-off]; }
                __syncthreads();
                shA[tid]=vT+uT; shB[tid]=vS+uS;
                __syncthreads();
            }
            float Ttot = shA[NTHR-1], Stot = shB[NTHR-1];
            float rT = tid? shA[tid-1]:0.f;
            float rS = tid? shB[tid-1]:0.f;
            #pragma unroll
            for (int m=0;m<4;m++){
                rT += bt[m]; rS += bs[m];
                shT[4*tid+m] = make_float4(rT, rS, bt[m], bs[m]);  // (inclT, inclS, binT, binS)
            }
            __syncthreads();

            // L1 in bin space: elements of bin j see mirror bin 1023-j
            float contrib = 0.f;
            #pragma unroll
            for (int m=0;m<4;m++){
                int j = 4*tid+m;
                float4 bp = shT[(NBINS-1) - j];
                float pt = Ttot - bp.x + 0.5f*bp.z;
                float ps = Stot - bp.y + 0.5f*bp.w;
                contrib += bt[m]*(2.f*pt - Ttot) - bs[m]*(2.f*ps - Stot);
            }
            float l1f = blockSum(contrib, shR);

            // wait for Gram, then combine + reset everything
            if (tid == 0){
                while (*(volatile unsigned*)&g_gdone != NGB) { }
            }
            __threadfence();
            __syncthreads();
            if (tid == 0){
                double ce = g_ce / (double)BB;
                double kd = 0.0;
                #pragma unroll
                for (int k2=0;k2<KK;k2++){
                    double T = (double)(k2+1);
                    kd += (g_kl[k2] / (double)(BB*CC)) * (0.7*T*T) + ce * 0.3;
                }
                double tt2=g_tt, ss2=g_ss, ts2=g_ts;
                double l2 = 0.00025*(tt2*tt2 - 2.0*ts2*ts2 + ss2*ss2);
                out[0] = (float)(kd + 0.00025*(double)l1f + l2 + g_sub);
                // reset state for next graph replay
                g_tt = 0.0; g_ss = 0.0; g_ts = 0.0;
                g_ce = 0.0; g_sub = 0.0;
                #pragma unroll
                for (int k2=0;k2<KK;k2++) g_kl[k2] = 0.0;
                g_tkdone = 0u; g_adone = 0u; g_gdone = 0u;
            }
            // whole block zeroes merged hist (block 0 is its only reader)
            #pragma unroll
            for (int i=tid; i<NBINS; i+=NTHR) g_hist2[i] = make_float2(0.f, 0.f);
        }
    } else {
        // =================== Gram blocks: wait for tk/sk, then 4x4 tiles ===================
        if (tid == 0){
            while (*(volatile unsigned*)&g_tkdone != NAB) { }
        }
        __threadfence();
        __syncthreads();

        const int NTG = KK*16*16;   // 1280 (BxB in 4x4 tiles)
        const int NTH = KK*25*25;   // 3125 (CxC in 4x4 tiles)
        int gid = (bid-NAB)*NTHR + tid;
        float val = 0.f;
        if (gid < NTG){
            int k  = gid >> 8;
            int r  = gid & 255;
            int i0 = (r >> 4) << 2;
            int j0 = (r & 15) << 2;
            const float* T = g_tk + k*BB*CC;
            const float* S = g_sk + k*BB*CC;
            float acc[16];
            #pragma unroll
            for (int q=0;q<16;q++) acc[q]=0.f;
            for (int c4=0;c4<CC;c4+=4){
                float4 Ti[4], Tj[4], Si[4], Sj[4];
                #pragma unroll
                for (int d2=0;d2<4;d2++){
                    Ti[d2]=*(const float4*)(T+(i0+d2)*CC+c4);
                    Tj[d2]=*(const float4*)(T+(j0+d2)*CC+c4);
                    Si[d2]=*(const float4*)(S+(i0+d2)*CC+c4);
                    Sj[d2]=*(const float4*)(S+(j0+d2)*CC+c4);
                }
                #pragma unroll
                for (int di=0;di<4;di++)
                    #pragma unroll
                    for (int dj=0;dj<4;dj++)
                        acc[di*4+dj] += Ti[di].x*Tj[dj].x - Si[di].x*Sj[dj].x
                                      + Ti[di].y*Tj[dj].y - Si[di].y*Sj[dj].y
                                      + Ti[di].z*Tj[dj].z - Si[di].z*Sj[dj].z
                                      + Ti[di].w*Tj[dj].w - Si[di].w*Sj[dj].w;
            }
            #pragma unroll
            for (int q=0;q<16;q++) val += acc[q]*acc[q];
        } else if (gid < NTG + NTH){
            int u  = gid - NTG;
            int k  = u / 625;
            int r  = u - k*625;
            int i0 = (r / 25) * 4;
            int j0 = (r % 25) * 4;
            const float* T = g_tk + k*BB*CC;
            const float* S = g_sk + k*BB*CC;
            float acc[16];
            #pragma unroll
            for (int q=0;q<16;q++) acc[q]=0.f;
            for (int b2=0;b2<BB;b2++){
                float4 t4i = *(const float4*)(T + b2*CC + i0);
                float4 t4j = *(const float4*)(T + b2*CC + j0);
                float4 s4i = *(const float4*)(S + b2*CC + i0);
                float4 s4j = *(const float4*)(S + b2*CC + j0);
                float ti[4]={t4i.x,t4i.y,t4i.z,t4i.w};
                float tj[4]={t4j.x,t4j.y,t4j.z,t4j.w};
                float si[4]={s4i.x,s4i.y,s4i.z,s4i.w};
                float sj[4]={s4j.x,s4j.y,s4j.z,s4j.w};
                #pragma unroll
                for (int di=0;di<4;di++)
                    #pragma unroll
                    for (int dj=0;dj<4;dj++)
                        acc[di*4+dj] += ti[di]*tj[dj] - si[di]*sj[dj];
            }
            #pragma unroll
            for (int q=0;q<16;q++) val += acc[q]*acc[q];
        }
        float r2 = blockSum(val, shR);
        if (tid==0){
            atomicAdd(&g_sub, (double)r2);
            __threadfence();
            atomicAdd(&g_gdone, 1u);
        }
    }
}

// ---------------- launch ----------------
extern "C" void kernel_launch(void* const* d_in, const int* in_sizes, int n_in,
                              void* d_out, int out_size){
    (void)in_sizes; (void)n_in; (void)out_size;
    const float* ls  = (const float*)d_in[0];  // logits_student [64,100]
    const float* lt  = (const float*)d_in[1];  // logits_teacher [64,100]
    const int*   tgt = (const int*)  d_in[2];  // target [64]
    float* out = (float*)d_out;

    fused_kernel<<<NBLK, NTHR>>>(ls, lt, tgt, out);
}

// round 13
// speedup vs baseline: 2.2010x; 1.2971x over previous
#include <cuda_runtime.h>
#include <math.h>
#include <float.h>

#define BB 64
#define CC 100
#define KK 5
#define NN (BB*CC*KK)      // 32000
#define NBINS 1024
#define NAB 40             // Phase-A blocks (320 warp tasks / 8)
#define NGB 36             // Gram blocks (9015 sym-tile items / 256)
#define NBLK (NAB+NGB)     // 76
#define NTHR 256
#define DMINF (-8.0f)
#define INVWF 64.0f        // NBINS / 16; symmetric range => binOf(-d) == 1023 - binOf(d)

#define NTG2 (KK*528)      // 2640: G upper-tri 2x2 tiles (32*33/2 per k)
#define NTH2 (KK*1275)     // 6375: H upper-tri 2x2 tiles (50*51/2 per k)

// ---------------- device scratch (no allocs allowed) ----------------
__device__ float2 g_hist2[NBINS];      // (sumT, sumS) merged from block-private hists
__device__ float  g_tk[KK*BB*CC], g_sk[KK*BB*CC];   // [k][b][c]
__device__ double g_tt, g_ss, g_ts, g_kl[KK], g_ce, g_sub;
__device__ unsigned g_tkdone;          // tk/sk stores complete
__device__ unsigned g_adone;           // full Phase-A complete (hist + scalars merged)
__device__ unsigned g_gdone;           // Gram blocks complete

__device__ __forceinline__ int binOf(float x){
    int j = (int)floorf((x - DMINF) * INVWF);
    return min(max(j, 0), NBINS-1);
}

__device__ __forceinline__ float blockSum(float v, float* shR){
    int lane = threadIdx.x & 31, w = threadIdx.x >> 5;
    #pragma unroll
    for (int o=16;o;o>>=1) v += __shfl_down_sync(0xffffffffu, v, o);
    if (lane==0) shR[w] = v;
    __syncthreads();
    float r = 0.f;
    if (threadIdx.x==0){
        #pragma unroll
        for (int i=0;i<NTHR/32;i++) r += shR[i];
    }
    __syncthreads();
    return r;   // valid on tid 0 only
}

__global__ void __launch_bounds__(NTHR)
fused_kernel(const float* __restrict__ ls, const float* __restrict__ lt,
             const int* __restrict__ tgt, float* __restrict__ out)
{
    __shared__ float4 shT[NBINS];          // 16 KB: block0 scan table; low 8 KB = A private hist
    __shared__ float  shA[NTHR], shB[NTHR];
    __shared__ float  shR[NTHR/32];
    __shared__ float  shKL[KK], shTT, shSS, shTS;

    const int tid  = threadIdx.x;
    const int bid  = blockIdx.x;
    const int lane = tid & 31;
    const int wid  = tid >> 5;

    if (bid < NAB){
        // ============ Phase A: softmax + KD + L2 dots + private smem hist ============
        float2* shH = (float2*)shT;        // 1024-bin private histogram (8 KB)
        #pragma unroll
        for (int i=tid; i<NBINS; i+=NTHR) shH[i] = make_float2(0.f, 0.f);
        if (tid < KK) shKL[tid] = 0.f;
        if (tid == KK)   shTT = 0.f;
        if (tid == KK+1) shSS = 0.f;
        if (tid == KK+2) shTS = 0.f;
        __syncthreads();

        int gw = bid*(NTHR/32) + wid;      // always < 320
        int b = gw / KK, k = gw % KK;
        float invT = 1.0f / (float)(k+1);
        float av[4], bv[4];
        float amax = -FLT_MAX, bmax = -FLT_MAX;
        #pragma unroll
        for (int q=0;q<4;q++){
            int c = lane + 32*q;
            bool ok = c < CC;
            av[q] = ok ? ls[b*CC+c]*invT : -FLT_MAX;
            bv[q] = ok ? lt[b*CC+c]*invT : -FLT_MAX;
            amax = fmaxf(amax, av[q]);
            bmax = fmaxf(bmax, bv[q]);
        }
        #pragma unroll
        for (int o=16;o;o>>=1){
            amax = fmaxf(amax, __shfl_xor_sync(0xffffffffu, amax, o));
            bmax = fmaxf(bmax, __shfl_xor_sync(0xffffffffu, bmax, o));
        }
        float ea[4], eb[4], sumA = 0.f, sumB = 0.f;
        #pragma unroll
        for (int q=0;q<4;q++){
            int c = lane + 32*q;
            ea[q] = (c<CC) ? expf(av[q]-amax) : 0.f;
            eb[q] = (c<CC) ? expf(bv[q]-bmax) : 0.f;
            sumA += ea[q]; sumB += eb[q];
        }
        #pragma unroll
        for (int o=16;o;o>>=1){
            sumA += __shfl_xor_sync(0xffffffffu, sumA, o);
            sumB += __shfl_xor_sync(0xffffffffu, sumB, o);
        }
        float lA = logf(sumA), lB = logf(sumB);
        float rA = 1.f/sumA, rB = 1.f/sumB;
        int tg = (k==0) ? tgt[b] : -1;
        float kl=0.f, tt=0.f, ssv=0.f, tsv=0.f;
        #pragma unroll
        for (int q=0;q<4;q++){
            int c = lane + 32*q;
            if (c < CC){
                float lq = av[q]-amax-lA;
                float lp = bv[q]-bmax-lB;
                float sv = ea[q]*rA;
                float tv = eb[q]*rB;
                float dv = lp - lq;
                int i2 = (k*BB + b)*CC + c;
                g_tk[i2]=tv; g_sk[i2]=sv;
                int j = binOf(dv);
                atomicAdd(&shH[j].x, tv);
                atomicAdd(&shH[j].y, sv);
                kl  += tv*dv;
                tt  += tv*tv;
                ssv += sv*sv;
                tsv += tv*sv;
                if (c == tg) atomicAdd(&g_ce, (double)(-lq));
            }
        }
        #pragma unroll
        for (int o=16;o;o>>=1){
            kl  += __shfl_xor_sync(0xffffffffu, kl,  o);
            tt  += __shfl_xor_sync(0xffffffffu, tt,  o);
            ssv += __shfl_xor_sync(0xffffffffu, ssv, o);
            tsv += __shfl_xor_sync(0xffffffffu, tsv, o);
        }
        if (lane==0){
            atomicAdd(&shKL[k], kl);
            atomicAdd(&shTT, tt);
            atomicAdd(&shSS, ssv);
            atomicAdd(&shTS, tsv);
        }
        __threadfence();                    // tk/sk stores visible
        __syncthreads();
        if (tid==0) atomicAdd(&g_tkdone, 1u);   // early release for Gram blocks

        // merge private hist -> global (skip empty bins; contention <= 40/address)
        #pragma unroll
        for (int i=tid; i<NBINS; i+=NTHR){
            float2 h = shH[i];
            if (h.x != 0.f || h.y != 0.f){
                atomicAdd(&g_hist2[i].x, h.x);
                atomicAdd(&g_hist2[i].y, h.y);
            }
        }
        if (tid < KK)     atomicAdd(&g_kl[tid], (double)shKL[tid]);
        if (tid == KK)    atomicAdd(&g_tt, (double)shTT);
        if (tid == KK+1)  atomicAdd(&g_ss, (double)shSS);
        if (tid == KK+2)  atomicAdd(&g_ts, (double)shTS);
        __threadfence();
        __syncthreads();
        if (tid==0) atomicAdd(&g_adone, 1u);

        if (bid == 0){
            // ============ Block 0: bin-space L1 + final combine ============
            if (tid == 0){
                while (*(volatile unsigned*)&g_adone != NAB) { }
            }
            __threadfence();
            __syncthreads();

            float4 A0 = ((const float4*)g_hist2)[2*tid];     // bins 4t, 4t+1
            float4 A1 = ((const float4*)g_hist2)[2*tid+1];   // bins 4t+2, 4t+3
            float bt[4] = {A0.x, A0.z, A1.x, A1.z};
            float bs[4] = {A0.y, A0.w, A1.y, A1.w};
            shA[tid] = bt[0]+bt[1]+bt[2]+bt[3];
            shB[tid] = bs[0]+bs[1]+bs[2]+bs[3];
            __syncthreads();
            #pragma unroll
            for (int off=1; off<NTHR; off<<=1){
                float vT=shA[tid], vS=shB[tid];
                float uT=0.f,uS=0.f;
                if (tid>=off){ uT=shA[tid-off]; uS=shB[tid-off]; }
                __syncthreads();
                shA[tid]=vT+uT; shB[tid]=vS+uS;
                __syncthreads();
            }
            float Ttot = shA[NTHR-1], Stot = shB[NTHR-1];
            float rT = tid? shA[tid-1]:0.f;
            float rS = tid? shB[tid-1]:0.f;
            #pragma unroll
            for (int m=0;m<4;m++){
                rT += bt[m]; rS += bs[m];
                shT[4*tid+m] = make_float4(rT, rS, bt[m], bs[m]);
            }
            __syncthreads();

            // L1 in bin space: elements of bin j see mirror bin 1023-j
            float contrib = 0.f;
            #pragma unroll
            for (int m=0;m<4;m++){
                int j = 4*tid+m;
                float4 bp = shT[(NBINS-1) - j];
                float pt = Ttot - bp.x + 0.5f*bp.z;
                float ps = Stot - bp.y + 0.5f*bp.w;
                contrib += bt[m]*(2.f*pt - Ttot) - bs[m]*(2.f*ps - Stot);
            }
            float l1f = blockSum(contrib, shR);

            if (tid == 0){
                while (*(volatile unsigned*)&g_gdone != NGB) { }
            }
            __threadfence();
            __syncthreads();
            if (tid == 0){
                double ce = g_ce / (double)BB;
                double kd = 0.0;
                #pragma unroll
                for (int k2=0;k2<KK;k2++){
                    double T = (double)(k2+1);
                    kd += (g_kl[k2] / (double)(BB*CC)) * (0.7*T*T) + ce * 0.3;
                }
                double tt2=g_tt, ss2=g_ss, ts2=g_ts;
                double l2 = 0.00025*(tt2*tt2 - 2.0*ts2*ts2 + ss2*ss2);
                out[0] = (float)(kd + 0.00025*(double)l1f + l2 + g_sub);
                g_tt = 0.0; g_ss = 0.0; g_ts = 0.0;
                g_ce = 0.0; g_sub = 0.0;
                #pragma unroll
                for (int k2=0;k2<KK;k2++) g_kl[k2] = 0.0;
                g_tkdone = 0u; g_adone = 0u; g_gdone = 0u;
            }
            #pragma unroll
            for (int i=tid; i<NBINS; i+=NTHR) g_hist2[i] = make_float2(0.f, 0.f);
        }
    } else {
        // ============ Gram blocks: symmetric 2x2 upper-triangle tiles ============
        if (tid == 0){
            while (*(volatile unsigned*)&g_tkdone != NAB) { }
        }
        __threadfence();
        __syncthreads();

        int gid = (bid-NAB)*NTHR + tid;
        float val = 0.f;
        if (gid < NTG2){
            // G = T T^T - S S^T (BxB, symmetric): tile (a,b), a<=b, coords in 0..31
            int k = gid / 528;
            int p = gid - k*528;
            int a = 0;
            while (p >= 32-a){ p -= 32-a; a++; }
            int b2 = a + p;
            int i0 = 2*a, j0 = 2*b2;
            const float* T = g_tk + k*BB*CC;
            const float* S = g_sk + k*BB*CC;
            float a00=0.f,a01=0.f,a10=0.f,a11=0.f;
            for (int c4=0;c4<CC;c4+=4){
                float4 Ti0=*(const float4*)(T+ i0   *CC+c4);
                float4 Ti1=*(const float4*)(T+(i0+1)*CC+c4);
                float4 Tj0=*(const float4*)(T+ j0   *CC+c4);
                float4 Tj1=*(const float4*)(T+(j0+1)*CC+c4);
                float4 Si0=*(const float4*)(S+ i0   *CC+c4);
                float4 Si1=*(const float4*)(S+(i0+1)*CC+c4);
                float4 Sj0=*(const float4*)(S+ j0   *CC+c4);
                float4 Sj1=*(const float4*)(S+(j0+1)*CC+c4);
                a00 += Ti0.x*Tj0.x - Si0.x*Sj0.x + Ti0.y*Tj0.y - Si0.y*Sj0.y
                     + Ti0.z*Tj0.z - Si0.z*Sj0.z + Ti0.w*Tj0.w - Si0.w*Sj0.w;
                a01 += Ti0.x*Tj1.x - Si0.x*Sj1.x + Ti0.y*Tj1.y - Si0.y*Sj1.y
                     + Ti0.z*Tj1.z - Si0.z*Sj1.z + Ti0.w*Tj1.w - Si0.w*Sj1.w;
                a10 += Ti1.x*Tj0.x - Si1.x*Sj0.x + Ti1.y*Tj0.y - Si1.y*Sj0.y
                     + Ti1.z*Tj0.z - Si1.z*Sj0.z + Ti1.w*Tj0.w - Si1.w*Sj0.w;
                a11 += Ti1.x*Tj1.x - Si1.x*Sj1.x + Ti1.y*Tj1.y - Si1.y*Sj1.y
                     + Ti1.z*Tj1.z - Si1.z*Sj1.z + Ti1.w*Tj1.w - Si1.w*Sj1.w;
            }
            float w = (a==b2) ? 1.f : 2.f;
            val = w*(a00*a00 + a01*a01 + a10*a10 + a11*a11);
        } else if (gid < NTG2 + NTH2){
            // H = T^T T - S^T S (CxC, symmetric): tile (a,b), a<=b, coords in 0..49
            int u = gid - NTG2;
            int k = u / 1275;
            int p = u - k*1275;
            int a = 0;
            while (p >= 50-a){ p -= 50-a; a++; }
            int b2 = a + p;
            int i0 = 2*a, j0 = 2*b2;
            const float* T = g_tk + k*BB*CC;
            const float* S = g_sk + k*BB*CC;
            float a00=0.f,a01=0.f,a10=0.f,a11=0.f;
            for (int r2=0;r2<BB;r2++){
                const float* Tr = T + r2*CC;
                const float* Sr = S + r2*CC;
                float2 ti = *(const float2*)(Tr + i0);   // i0 even, CC even -> aligned
                float2 tj = *(const float2*)(Tr + j0);
                float2 si = *(const float2*)(Sr + i0);
                float2 sj = *(const float2*)(Sr + j0);
                a00 += ti.x*tj.x - si.x*sj.x;
                a01 += ti.x*tj.y - si.x*sj.y;
                a10 += ti.y*tj.x - si.y*sj.x;
                a11 += ti.y*tj.y - si.y*sj.y;
            }
            float w = (a==b2) ? 1.f : 2.f;
            val = w*(a00*a00 + a01*a01 + a10*a10 + a11*a11);
        }
        float r2s = blockSum(val, shR);
        if (tid==0){
            atomicAdd(&g_sub, (double)r2s);
            __threadfence();
            atomicAdd(&g_gdone, 1u);
        }
    }
}

// ---------------- launch ----------------
extern "C" void kernel_launch(void* const* d_in, const int* in_sizes, int n_in,
                              void* d_out, int out_size){
    (void)in_sizes; (void)n_in; (void)out_size;
    const float* ls  = (const float*)d_in[0];  // logits_student [64,100]
    const float* lt  = (const float*)d_in[1];  // logits_teacher [64,100]
    const int*   tgt = (const int*)  d_in[2];  // target [64]
    float* out = (float*)d_out;

    fused_kernel<<<NBLK, NTHR>>>(ls, lt, tgt, out);
}

// round 14
// speedup vs baseline: 2.9409x; 1.3361x over previous
#include <cuda_runtime.h>
#include <math.h>
#include <float.h>

#define BB 64
#define CC 100
#define KK 5
#define NN (BB*CC*KK)      // 32000
#define NBINS 1024
#define NAB 40             // Phase-A blocks (320 warp tasks / 8)
#define NGB 71             // Gram blocks (18030 half-tile items / 256)
#define NBLK (NAB+NGB)     // 111
#define NTHR 256
#define DMINF (-8.0f)
#define INVWF 64.0f        // NBINS / 16; symmetric range => binOf(-d) == 1023 - binOf(d)

#define NTG2 (KK*528)      // 2640: G upper-tri 2x2 tiles (32*33/2 per k)
#define NTH2 (KK*1275)     // 6375: H upper-tri 2x2 tiles (50*51/2 per k)
#define NTILES (NTG2+NTH2) // 9015 tiles, 2 threads each

// ---------------- device scratch (no allocs allowed) ----------------
__device__ float2 g_hist2[NBINS];      // (sumT, sumS) merged from block-private hists
__device__ float  g_tk[KK*BB*CC], g_sk[KK*BB*CC];   // [k][b][c]
__device__ double g_tt, g_ss, g_ts, g_kl[KK], g_ce, g_sub;
__device__ unsigned g_tkdone;          // tk/sk stores complete
__device__ unsigned g_adone;           // full Phase-A complete (hist + scalars merged)
__device__ unsigned g_gdone;           // Gram blocks complete

__device__ __forceinline__ int binOf(float x){
    int j = (int)floorf((x - DMINF) * INVWF);
    return min(max(j, 0), NBINS-1);
}

__device__ __forceinline__ float blockSum(float v, float* shR){
    int lane = threadIdx.x & 31, w = threadIdx.x >> 5;
    #pragma unroll
    for (int o=16;o;o>>=1) v += __shfl_down_sync(0xffffffffu, v, o);
    if (lane==0) shR[w] = v;
    __syncthreads();
    float r = 0.f;
    if (threadIdx.x==0){
        #pragma unroll
        for (int i=0;i<NTHR/32;i++) r += shR[i];
    }
    __syncthreads();
    return r;   // valid on tid 0 only
}

__global__ void __launch_bounds__(NTHR)
fused_kernel(const float* __restrict__ ls, const float* __restrict__ lt,
             const int* __restrict__ tgt, float* __restrict__ out)
{
    __shared__ float4 shT[NBINS];          // 16 KB: block0 scan table; low 8 KB = A private hist
    __shared__ float  shA[NTHR], shB[NTHR];
    __shared__ float  shR[NTHR/32];
    __shared__ float  shKL[KK], shTT, shSS, shTS;

    const int tid  = threadIdx.x;
    const int bid  = blockIdx.x;
    const int lane = tid & 31;
    const int wid  = tid >> 5;

    if (bid < NAB){
        // ============ Phase A: softmax + KD + L2 dots + private smem hist ============
        float2* shH = (float2*)shT;        // 1024-bin private histogram (8 KB)
        #pragma unroll
        for (int i=tid; i<NBINS; i+=NTHR) shH[i] = make_float2(0.f, 0.f);
        if (tid < KK) shKL[tid] = 0.f;
        if (tid == KK)   shTT = 0.f;
        if (tid == KK+1) shSS = 0.f;
        if (tid == KK+2) shTS = 0.f;
        __syncthreads();

        int gw = bid*(NTHR/32) + wid;      // always < 320
        int b = gw / KK, k = gw % KK;
        float invT = 1.0f / (float)(k+1);
        float av[4], bv[4];
        float amax = -FLT_MAX, bmax = -FLT_MAX;
        #pragma unroll
        for (int q=0;q<4;q++){
            int c = lane + 32*q;
            bool ok = c < CC;
            av[q] = ok ? ls[b*CC+c]*invT : -FLT_MAX;
            bv[q] = ok ? lt[b*CC+c]*invT : -FLT_MAX;
            amax = fmaxf(amax, av[q]);
            bmax = fmaxf(bmax, bv[q]);
        }
        #pragma unroll
        for (int o=16;o;o>>=1){
            amax = fmaxf(amax, __shfl_xor_sync(0xffffffffu, amax, o));
            bmax = fmaxf(bmax, __shfl_xor_sync(0xffffffffu, bmax, o));
        }
        float ea[4], eb[4], sumA = 0.f, sumB = 0.f;
        #pragma unroll
        for (int q=0;q<4;q++){
            int c = lane + 32*q;
            ea[q] = (c<CC) ? expf(av[q]-amax) : 0.f;
            eb[q] = (c<CC) ? expf(bv[q]-bmax) : 0.f;
            sumA += ea[q]; sumB += eb[q];
        }
        #pragma unroll
        for (int o=16;o;o>>=1){
            sumA += __shfl_xor_sync(0xffffffffu, sumA, o);
            sumB += __shfl_xor_sync(0xffffffffu, sumB, o);
        }
        float lA = logf(sumA), lB = logf(sumB);
        float rA = 1.f/sumA, rB = 1.f/sumB;
        int tg = (k==0) ? tgt[b] : -1;
        float kl=0.f, tt=0.f, ssv=0.f, tsv=0.f;
        #pragma unroll
        for (int q=0;q<4;q++){
            int c = lane + 32*q;
            if (c < CC){
                float lq = av[q]-amax-lA;
                float lp = bv[q]-bmax-lB;
                float sv = ea[q]*rA;
                float tv = eb[q]*rB;
                float dv = lp - lq;
                int i2 = (k*BB + b)*CC + c;
                g_tk[i2]=tv; g_sk[i2]=sv;
                int j = binOf(dv);
                atomicAdd(&shH[j].x, tv);
                atomicAdd(&shH[j].y, sv);
                kl  += tv*dv;
                tt  += tv*tv;
                ssv += sv*sv;
                tsv += tv*sv;
                if (c == tg) atomicAdd(&g_ce, (double)(-lq));
            }
        }
        #pragma unroll
        for (int o=16;o;o>>=1){
            kl  += __shfl_xor_sync(0xffffffffu, kl,  o);
            tt  += __shfl_xor_sync(0xffffffffu, tt,  o);
            ssv += __shfl_xor_sync(0xffffffffu, ssv, o);
            tsv += __shfl_xor_sync(0xffffffffu, tsv, o);
        }
        if (lane==0){
            atomicAdd(&shKL[k], kl);
            atomicAdd(&shTT, tt);
            atomicAdd(&shSS, ssv);
            atomicAdd(&shTS, tsv);
        }
        __threadfence();                    // tk/sk stores visible
        __syncthreads();
        if (tid==0) atomicAdd(&g_tkdone, 1u);   // early release for Gram blocks

        // merge private hist -> global (skip empty bins; contention <= 40/address)
        #pragma unroll
        for (int i=tid; i<NBINS; i+=NTHR){
            float2 h = shH[i];
            if (h.x != 0.f || h.y != 0.f){
                atomicAdd(&g_hist2[i].x, h.x);
                atomicAdd(&g_hist2[i].y, h.y);
            }
        }
        if (tid < KK)     atomicAdd(&g_kl[tid], (double)shKL[tid]);
        if (tid == KK)    atomicAdd(&g_tt, (double)shTT);
        if (tid == KK+1)  atomicAdd(&g_ss, (double)shSS);
        if (tid == KK+2)  atomicAdd(&g_ts, (double)shTS);
        __threadfence();
        __syncthreads();
        if (tid==0) atomicAdd(&g_adone, 1u);

        if (bid == 0){
            // ============ Block 0: bin-space L1 + final combine ============
            if (tid == 0){
                while (*(volatile unsigned*)&g_adone != NAB) { }
            }
            __threadfence();
            __syncthreads();

            float4 A0 = ((const float4*)g_hist2)[2*tid];     // bins 4t, 4t+1
            float4 A1 = ((const float4*)g_hist2)[2*tid+1];   // bins 4t+2, 4t+3
            float bt[4] = {A0.x, A0.z, A1.x, A1.z};
            float bs[4] = {A0.y, A0.w, A1.y, A1.w};
            shA[tid] = bt[0]+bt[1]+bt[2]+bt[3];
            shB[tid] = bs[0]+bs[1]+bs[2]+bs[3];
            __syncthreads();
            #pragma unroll
            for (int off=1; off<NTHR; off<<=1){
                float vT=shA[tid], vS=shB[tid];
                float uT=0.f,uS=0.f;
                if (tid>=off){ uT=shA[tid-off]; uS=shB[tid-off]; }
                __syncthreads();
                shA[tid]=vT+uT; shB[tid]=vS+uS;
                __syncthreads();
            }
            float Ttot = shA[NTHR-1], Stot = shB[NTHR-1];
            float rT = tid? shA[tid-1]:0.f;
            float rS = tid? shB[tid-1]:0.f;
            #pragma unroll
            for (int m=0;m<4;m++){
                rT += bt[m]; rS += bs[m];
                shT[4*tid+m] = make_float4(rT, rS, bt[m], bs[m]);
            }
            __syncthreads();

            // L1 in bin space: elements of bin j see mirror bin 1023-j
            float contrib = 0.f;
            #pragma unroll
            for (int m=0;m<4;m++){
                int j = 4*tid+m;
                float4 bp = shT[(NBINS-1) - j];
                float pt = Ttot - bp.x + 0.5f*bp.z;
                float ps = Stot - bp.y + 0.5f*bp.w;
                contrib += bt[m]*(2.f*pt - Ttot) - bs[m]*(2.f*ps - Stot);
            }
            float l1f = blockSum(contrib, shR);

            if (tid == 0){
                while (*(volatile unsigned*)&g_gdone != NGB) { }
            }
            __threadfence();
            __syncthreads();
            if (tid == 0){
                double ce = g_ce / (double)BB;
                double kd = 0.0;
                #pragma unroll
                for (int k2=0;k2<KK;k2++){
                    double T = (double)(k2+1);
                    kd += (g_kl[k2] / (double)(BB*CC)) * (0.7*T*T) + ce * 0.3;
                }
                double tt2=g_tt, ss2=g_ss, ts2=g_ts;
                double l2 = 0.00025*(tt2*tt2 - 2.0*ts2*ts2 + ss2*ss2);
                out[0] = (float)(kd + 0.00025*(double)l1f + l2 + g_sub);
                g_tt = 0.0; g_ss = 0.0; g_ts = 0.0;
                g_ce = 0.0; g_sub = 0.0;
                #pragma unroll
                for (int k2=0;k2<KK;k2++) g_kl[k2] = 0.0;
                g_tkdone = 0u; g_adone = 0u; g_gdone = 0u;
            }
            #pragma unroll
            for (int i=tid; i<NBINS; i+=NTHR) g_hist2[i] = make_float2(0.f, 0.f);
        }
    } else {
        // ====== Gram blocks: symmetric 2x2 upper-tri tiles, 2 threads per tile ======
        if (tid == 0){
            while (*(volatile unsigned*)&g_tkdone != NAB) { }
        }
        __threadfence();
        __syncthreads();

        int gid  = (bid-NAB)*NTHR + tid;
        int pair = gid >> 1;               // tile index
        int half = gid & 1;                // which half of the contraction
        float a00=0.f,a01=0.f,a10=0.f,a11=0.f;
        float w = 0.f;
        if (pair < NTG2){
            // G = T T^T - S S^T (BxB, symmetric): tile (a,b), a<=b, coords 0..31
            int k = pair / 528;
            int p = pair - k*528;
            int a = 0;
            while (p >= 32-a){ p -= 32-a; a++; }
            int b2 = a + p;
            int i0 = 2*a, j0 = 2*b2;
            const float* T = g_tk + k*BB*CC;
            const float* S = g_sk + k*BB*CC;
            int c4lo = half ? 52 : 0;
            int c4hi = half ? CC : 52;
            for (int c4=c4lo;c4<c4hi;c4+=4){
                float4 Ti0=*(const float4*)(T+ i0   *CC+c4);
                float4 Ti1=*(const float4*)(T+(i0+1)*CC+c4);
                float4 Tj0=*(const float4*)(T+ j0   *CC+c4);
                float4 Tj1=*(const float4*)(T+(j0+1)*CC+c4);
                float4 Si0=*(const float4*)(S+ i0   *CC+c4);
                float4 Si1=*(const float4*)(S+(i0+1)*CC+c4);
                float4 Sj0=*(const float4*)(S+ j0   *CC+c4);
                float4 Sj1=*(const float4*)(S+(j0+1)*CC+c4);
                a00 += Ti0.x*Tj0.x - Si0.x*Sj0.x + Ti0.y*Tj0.y - Si0.y*Sj0.y
                     + Ti0.z*Tj0.z - Si0.z*Sj0.z + Ti0.w*Tj0.w - Si0.w*Sj0.w;
                a01 += Ti0.x*Tj1.x - Si0.x*Sj1.x + Ti0.y*Tj1.y - Si0.y*Sj1.y
                     + Ti0.z*Tj1.z - Si0.z*Sj1.z + Ti0.w*Tj1.w - Si0.w*Sj1.w;
                a10 += Ti1.x*Tj0.x - Si1.x*Sj0.x + Ti1.y*Tj0.y - Si1.y*Sj0.y
                     + Ti1.z*Tj0.z - Si1.z*Sj0.z + Ti1.w*Tj0.w - Si1.w*Sj0.w;
                a11 += Ti1.x*Tj1.x - Si1.x*Sj1.x + Ti1.y*Tj1.y - Si1.y*Sj1.y
                     + Ti1.z*Tj1.z - Si1.z*Sj1.z + Ti1.w*Tj1.w - Si1.w*Sj1.w;
            }
            w = (a==b2) ? 1.f : 2.f;
        } else if (pair < NTILES){
            // H = T^T T - S^T S (CxC, symmetric): tile (a,b), a<=b, coords 0..49
            int u = pair - NTG2;
            int k = u / 1275;
            int p = u - k*1275;
            int a = 0;
            while (p >= 50-a){ p -= 50-a; a++; }
            int b2 = a + p;
            int i0 = 2*a, j0 = 2*b2;
            const float* T = g_tk + k*BB*CC;
            const float* S = g_sk + k*BB*CC;
            int rlo = half*32, rhi = rlo+32;
            for (int r2=rlo;r2<rhi;r2++){
                const float* Tr = T + r2*CC;
                const float* Sr = S + r2*CC;
                float2 ti = *(const float2*)(Tr + i0);
                float2 tj = *(const float2*)(Tr + j0);
                float2 si = *(const float2*)(Sr + i0);
                float2 sj = *(const float2*)(Sr + j0);
                a00 += ti.x*tj.x - si.x*sj.x;
                a01 += ti.x*tj.y - si.x*sj.y;
                a10 += ti.y*tj.x - si.y*sj.x;
                a11 += ti.y*tj.y - si.y*sj.y;
            }
            w = (a==b2) ? 1.f : 2.f;
        }
        // combine halves (pair mates are adjacent lanes of the same warp)
        a00 += __shfl_xor_sync(0xffffffffu, a00, 1);
        a01 += __shfl_xor_sync(0xffffffffu, a01, 1);
        a10 += __shfl_xor_sync(0xffffffffu, a10, 1);
        a11 += __shfl_xor_sync(0xffffffffu, a11, 1);
        float val = (half==0) ? w*(a00*a00 + a01*a01 + a10*a10 + a11*a11) : 0.f;
        float r2s = blockSum(val, shR);
        if (tid==0){
            atomicAdd(&g_sub, (double)r2s);
            __threadfence();
            atomicAdd(&g_gdone, 1u);
        }
    }
}

// ---------------- launch ----------------
extern "C" void kernel_launch(void* const* d_in, const int* in_sizes, int n_in,
                              void* d_out, int out_size){
    (void)in_sizes; (void)n_in; (void)out_size;
    const float* ls  = (const float*)d_in[0];  // logits_student [64,100]
    const float* lt  = (const float*)d_in[1];  // logits_teacher [64,100]
    const int*   tgt = (const int*)  d_in[2];  // target [64]
    float* out = (float*)d_out;

    fused_kernel<<<NBLK, NTHR>>>(ls, lt, tgt, out);
}

// round 16
// speedup vs baseline: 3.0544x; 1.0386x over previous
#include <cuda_runtime.h>
#include <math.h>
#include <float.h>

#define BB 64
#define CC 100
#define KK 5
#define NN (BB*CC*KK)      // 32000
#define NBINS 1024
#define NAB 40             // Phase-A blocks (320 warp tasks / 8)
#define NGB 42             // Gram blocks (2640 tiles * 4 threads / 256)
#define NBLK (NAB+NGB)     // 82
#define NTHR 256
#define DMINF (-8.0f)
#define INVWF 64.0f        // NBINS / 16; symmetric range => binOf(-d) == 1023 - binOf(d)

#define NTILES (KK*528)    // 2640: B x B upper-tri 2x2 tiles (32*33/2 per k)

// ---------------- device scratch (no allocs allowed) ----------------
__device__ float2 g_hist2[NBINS];      // (sumT, sumS) merged from block-private hists
__device__ float  g_tk[KK*BB*CC], g_sk[KK*BB*CC];   // [k][b][c]
__device__ double g_tt, g_ss, g_ts, g_kl[KK], g_ce, g_sub;
__device__ unsigned g_tkdone;          // tk/sk stores complete
__device__ unsigned g_adone;           // full Phase-A complete (hist + scalars merged)
__device__ unsigned g_gdone;           // Gram blocks complete

__device__ __forceinline__ int binOf(float x){
    int j = (int)floorf((x - DMINF) * INVWF);
    return min(max(j, 0), NBINS-1);
}

__device__ __forceinline__ float blockSum(float v, float* shR){
    int lane = threadIdx.x & 31, w = threadIdx.x >> 5;
    #pragma unroll
    for (int o=16;o;o>>=1) v += __shfl_down_sync(0xffffffffu, v, o);
    if (lane==0) shR[w] = v;
    __syncthreads();
    float r = 0.f;
    if (threadIdx.x==0){
        #pragma unroll
        for (int i=0;i<NTHR/32;i++) r += shR[i];
    }
    __syncthreads();
    return r;   // valid on tid 0 only
}

__global__ void __launch_bounds__(NTHR)
fused_kernel(const float* __restrict__ ls, const float* __restrict__ lt,
             const int* __restrict__ tgt, float* __restrict__ out)
{
    __shared__ float4 shT[NBINS];          // 16 KB: block0 scan table; low 8 KB = A private hist
    __shared__ float  shA[NTHR], shB[NTHR];
    __shared__ float  shR[NTHR/32];
    __shared__ float  shKL[KK], shTT, shSS, shTS;

    const int tid  = threadIdx.x;
    const int bid  = blockIdx.x;
    const int lane = tid & 31;
    const int wid  = tid >> 5;

    if (bid < NAB){
        // ============ Phase A: softmax + KD + L2 dots + private smem hist ============
        float2* shH = (float2*)shT;        // 1024-bin private histogram (8 KB)
        #pragma unroll
        for (int i=tid; i<NBINS; i+=NTHR) shH[i] = make_float2(0.f, 0.f);
        if (tid < KK) shKL[tid] = 0.f;
        if (tid == KK)   shTT = 0.f;
        if (tid == KK+1) shSS = 0.f;
        if (tid == KK+2) shTS = 0.f;
        __syncthreads();

        int gw = bid*(NTHR/32) + wid;      // always < 320
        int b = gw / KK, k = gw % KK;
        float invT = 1.0f / (float)(k+1);
        float av[4], bv[4];
        float amax = -FLT_MAX, bmax = -FLT_MAX;
        #pragma unroll
        for (int q=0;q<4;q++){
            int c = lane + 32*q;
            bool ok = c < CC;
            av[q] = ok ? ls[b*CC+c]*invT : -FLT_MAX;
            bv[q] = ok ? lt[b*CC+c]*invT : -FLT_MAX;
            amax = fmaxf(amax, av[q]);
            bmax = fmaxf(bmax, bv[q]);
        }
        #pragma unroll
        for (int o=16;o;o>>=1){
            amax = fmaxf(amax, __shfl_xor_sync(0xffffffffu, amax, o));
            bmax = fmaxf(bmax, __shfl_xor_sync(0xffffffffu, bmax, o));
        }
        float ea[4], eb[4], sumA = 0.f, sumB = 0.f;
        #pragma unroll
        for (int q=0;q<4;q++){
            int c = lane + 32*q;
            ea[q] = (c<CC) ? expf(av[q]-amax) : 0.f;
            eb[q] = (c<CC) ? expf(bv[q]-bmax) : 0.f;
            sumA += ea[q]; sumB += eb[q];
        }
        #pragma unroll
        for (int o=16;o;o>>=1){
            sumA += __shfl_xor_sync(0xffffffffu, sumA, o);
            sumB += __shfl_xor_sync(0xffffffffu, sumB, o);
        }
        float lA = logf(sumA), lB = logf(sumB);
        float rA = 1.f/sumA, rB = 1.f/sumB;
        int tg = (k==0) ? tgt[b] : -1;
        float kl=0.f, tt=0.f, ssv=0.f, tsv=0.f;
        #pragma unroll
        for (int q=0;q<4;q++){
            int c = lane + 32*q;
            if (c < CC){
                float lq = av[q]-amax-lA;
                float lp = bv[q]-bmax-lB;
                float sv = ea[q]*rA;
                float tv = eb[q]*rB;
                float dv = lp - lq;
                int i2 = (k*BB + b)*CC + c;
                g_tk[i2]=tv; g_sk[i2]=sv;
                int j = binOf(dv);
                atomicAdd(&shH[j].x, tv);
                atomicAdd(&shH[j].y, sv);
                kl  += tv*dv;
                tt  += tv*tv;
                ssv += sv*sv;
                tsv += tv*sv;
                if (c == tg) atomicAdd(&g_ce, (double)(-lq));
            }
        }
        #pragma unroll
        for (int o=16;o;o>>=1){
            kl  += __shfl_xor_sync(0xffffffffu, kl,  o);
            tt  += __shfl_xor_sync(0xffffffffu, tt,  o);
            ssv += __shfl_xor_sync(0xffffffffu, ssv, o);
            tsv += __shfl_xor_sync(0xffffffffu, tsv, o);
        }
        if (lane==0){
            atomicAdd(&shKL[k], kl);
            atomicAdd(&shTT, tt);
            atomicAdd(&shSS, ssv);
            atomicAdd(&shTS, tsv);
        }
        __threadfence();                    // tk/sk stores visible
        __syncthreads();
        if (tid==0) atomicAdd(&g_tkdone, 1u);   // early release for Gram blocks

        // merge private hist -> global (skip empty bins; contention <= 40/address)
        #pragma unroll
        for (int i=tid; i<NBINS; i+=NTHR){
            float2 h = shH[i];
            if (h.x != 0.f || h.y != 0.f){
                atomicAdd(&g_hist2[i].x, h.x);
                atomicAdd(&g_hist2[i].y, h.y);
            }
        }
        if (tid < KK)     atomicAdd(&g_kl[tid], (double)shKL[tid]);
        if (tid == KK)    atomicAdd(&g_tt, (double)shTT);
        if (tid == KK+1)  atomicAdd(&g_ss, (double)shSS);
        if (tid == KK+2)  atomicAdd(&g_ts, (double)shTS);
        __threadfence();
        __syncthreads();
        if (tid==0) atomicAdd(&g_adone, 1u);

        if (bid == 0){
            // ============ Block 0: bin-space L1 + final combine ============
            if (tid == 0){
                while (*(volatile unsigned*)&g_adone != NAB) { }
            }
            __threadfence();
            __syncthreads();

            float4 A0 = ((const float4*)g_hist2)[2*tid];     // bins 4t, 4t+1
            float4 A1 = ((const float4*)g_hist2)[2*tid+1];   // bins 4t+2, 4t+3
            float bt[4] = {A0.x, A0.z, A1.x, A1.z};
            float bs[4] = {A0.y, A0.w, A1.y, A1.w};
            shA[tid] = bt[0]+bt[1]+bt[2]+bt[3];
            shB[tid] = bs[0]+bs[1]+bs[2]+bs[3];
            __syncthreads();
            #pragma unroll
            for (int off=1; off<NTHR; off<<=1){
                float vT=shA[tid], vS=shB[tid];
                float uT=0.f,uS=0.f;
                if (tid>=off){ uT=shA[tid-off]; uS=shB[tid-off]; }
                __syncthreads();
                shA[tid]=vT+uT; shB[tid]=vS+uS;
                __syncthreads();
            }
            float Ttot = shA[NTHR-1], Stot = shB[NTHR-1];
            float rT = tid? shA[tid-1]:0.f;
            float rS = tid? shB[tid-1]:0.f;
            #pragma unroll
            for (int m=0;m<4;m++){
                rT += bt[m]; rS += bs[m];
                shT[4*tid+m] = make_float4(rT, rS, bt[m], bs[m]);
            }
            __syncthreads();

            // L1 in bin space: elements of bin j see mirror bin 1023-j
            float contrib = 0.f;
            #pragma unroll
            for (int m=0;m<4;m++){
                int j = 4*tid+m;
                float4 bp = shT[(NBINS-1) - j];
                float pt = Ttot - bp.x + 0.5f*bp.z;
                float ps = Stot - bp.y + 0.5f*bp.w;
                contrib += bt[m]*(2.f*pt - Ttot) - bs[m]*(2.f*ps - Stot);
            }
            float l1f = blockSum(contrib, shR);

            if (tid == 0){
                while (*(volatile unsigned*)&g_gdone != NGB) { }
            }
            __threadfence();
            __syncthreads();
            if (tid == 0){
                double ce = g_ce / (double)BB;
                double kd = 0.0;
                #pragma unroll
                for (int k2=0;k2<KK;k2++){
                    double T = (double)(k2+1);
                    kd += (g_kl[k2] / (double)(BB*CC)) * (0.7*T*T) + ce * 0.3;
                }
                double tt2=g_tt, ss2=g_ss, ts2=g_ts;
                double l2 = 0.00025*(tt2*tt2 - 2.0*ts2*ts2 + ss2*ss2);
                out[0] = (float)(kd + 0.00025*(double)l1f + l2 + g_sub);
                g_tt = 0.0; g_ss = 0.0; g_ts = 0.0;
                g_ce = 0.0; g_sub = 0.0;
                #pragma unroll
                for (int k2=0;k2<KK;k2++) g_kl[k2] = 0.0;
                g_tkdone = 0u; g_adone = 0u; g_gdone = 0u;
            }
            #pragma unroll
            for (int i=tid; i<NBINS; i+=NTHR) g_hist2[i] = make_float2(0.f, 0.f);
        }
    } else {
        // ====== Gram blocks: B x B tiles only, 4 threads per tile (quarter C-ranges) ======
        // M1 = T T^T, M2 = T S^T, M3 = S S^T  (64x64 each, per k)
        // loss_sub1 = sum ||M1-M3||_F^2
        // loss_sub2 = sum ||M1||^2 - 2||M2||^2 + ||M3||^2   (trace identity for C x C Gram)
        if (tid == 0){
            while (*(volatile unsigned*)&g_tkdone != NAB) { }
        }
        __threadfence();
        __syncthreads();

        int gid  = (bid-NAB)*NTHR + tid;
        int pair = gid >> 2;               // tile index
        int quar = gid & 3;                // quarter of the C contraction
        float m1[4]={0.f,0.f,0.f,0.f}, m3[4]={0.f,0.f,0.f,0.f};
        float m2f[4]={0.f,0.f,0.f,0.f}, m2b[4]={0.f,0.f,0.f,0.f};
        float w = 0.f;
        int isdiag = 0;
        if (pair < NTILES){
            int k = pair / 528;
            int p = pair - k*528;
            int a = 0;
            while (p >= 32-a){ p -= 32-a; a++; }
            int b2 = a + p;
            int i0 = 2*a, j0 = 2*b2;
            const float* T = g_tk + k*BB*CC;
            const float* S = g_sk + k*BB*CC;
            const int lo[5] = {0, 28, 52, 76, 100};
            int c4lo = lo[quar], c4hi = lo[quar+1];
            for (int c4=c4lo;c4<c4hi;c4+=4){
                float4 Ti0=*(const float4*)(T+ i0   *CC+c4);
                float4 Ti1=*(const float4*)(T+(i0+1)*CC+c4);
                float4 Tj0=*(const float4*)(T+ j0   *CC+c4);
                float4 Tj1=*(const float4*)(T+(j0+1)*CC+c4);
                float4 Si0=*(const float4*)(S+ i0   *CC+c4);
                float4 Si1=*(const float4*)(S+(i0+1)*CC+c4);
                float4 Sj0=*(const float4*)(S+ j0   *CC+c4);
                float4 Sj1=*(const float4*)(S+(j0+1)*CC+c4);
                // m1[r*2+s] += Ti_r . Tj_s   (T T^T)
                m1[0] += Ti0.x*Tj0.x + Ti0.y*Tj0.y + Ti0.z*Tj0.z + Ti0.w*Tj0.w;
                m1[1] += Ti0.x*Tj1.x + Ti0.y*Tj1.y + Ti0.z*Tj1.z + Ti0.w*Tj1.w;
                m1[2] += Ti1.x*Tj0.x + Ti1.y*Tj0.y + Ti1.z*Tj0.z + Ti1.w*Tj0.w;
                m1[3] += Ti1.x*Tj1.x + Ti1.y*Tj1.y + Ti1.z*Tj1.z + Ti1.w*Tj1.w;
                // m3[r*2+s] += Si_r . Sj_s   (S S^T)
                m3[0] += Si0.x*Sj0.x + Si0.y*Sj0.y + Si0.z*Sj0.z + Si0.w*Sj0.w;
                m3[1] += Si0.x*Sj1.x + Si0.y*Sj1.y + Si0.z*Sj1.z + Si0.w*Sj1.w;
                m3[2] += Si1.x*Sj0.x + Si1.y*Sj0.y + Si1.z*Sj0.z + Si1.w*Sj0.w;
                m3[3] += Si1.x*Sj1.x + Si1.y*Sj1.y + Si1.z*Sj1.z + Si1.w*Sj1.w;
                // m2f[r*2+s] += Ti_r . Sj_s  (M2[i][j])
                m2f[0] += Ti0.x*Sj0.x + Ti0.y*Sj0.y + Ti0.z*Sj0.z + Ti0.w*Sj0.w;
                m2f[1] += Ti0.x*Sj1.x + Ti0.y*Sj1.y + Ti0.z*Sj1.z + Ti0.w*Sj1.w;
                m2f[2] += Ti1.x*Sj0.x + Ti1.y*Sj0.y + Ti1.z*Sj0.z + Ti1.w*Sj0.w;
                m2f[3] += Ti1.x*Sj1.x + Ti1.y*Sj1.y + Ti1.z*Sj1.z + Ti1.w*Sj1.w;
                // m2b[r*2+s] += Tj_s . Si_r  (M2[j][i])
                m2b[0] += Tj0.x*Si0.x + Tj0.y*Si0.y + Tj0.z*Si0.z + Tj0.w*Si0.w;
                m2b[1] += Tj1.x*Si0.x + Tj1.y*Si0.y + Tj1.z*Si0.z + Tj1.w*Si0.w;
                m2b[2] += Tj0.x*Si1.x + Tj0.y*Si1.y + Tj0.z*Si1.z + Tj0.w*Si1.w;
                m2b[3] += Tj1.x*Si1.x + Tj1.y*Si1.y + Tj1.z*Si1.z + Tj1.w*Si1.w;
            }
            w = (a==b2) ? 1.f : 2.f;
            isdiag = (a==b2);
        }
        // combine quarters (4 consecutive lanes of the same warp)
        #pragma unroll
        for (int m=0;m<4;m++){
            m1[m]  += __shfl_xor_sync(0xffffffffu, m1[m],  1);
            m1[m]  += __shfl_xor_sync(0xffffffffu, m1[m],  2);
            m3[m]  += __shfl_xor_sync(0xffffffffu, m3[m],  1);
            m3[m]  += __shfl_xor_sync(0xffffffffu, m3[m],  2);
            m2f[m] += __shfl_xor_sync(0xffffffffu, m2f[m], 1);
            m2f[m] += __shfl_xor_sync(0xffffffffu, m2f[m], 2);
            m2b[m] += __shfl_xor_sync(0xffffffffu, m2b[m], 1);
            m2b[m] += __shfl_xor_sync(0xffffffffu, m2b[m], 2);
        }
        float val = 0.f;
        if (quar==0 && w > 0.f){
            float s1=0.f, sm1=0.f, sm3=0.f, s2f=0.f, s2b=0.f;
            #pragma unroll
            for (int m=0;m<4;m++){
                float dG = m1[m]-m3[m];
                s1  += dG*dG;
                sm1 += m1[m]*m1[m];
                sm3 += m3[m]*m3[m];
                s2f += m2f[m]*m2f[m];
                s2b += m2b[m]*m2b[m];
            }
            val = w*(s1 + sm1 + sm3) - 2.f*(isdiag ? s2f : (s2f + s2b));
        }
        float r2s = blockSum(val, shR);
        if (tid==0){
            atomicAdd(&g_sub, (double)r2s);
            __threadfence();
            atomicAdd(&g_gdone, 1u);
        }
    }
}

// ---------------- launch ----------------
extern "C" void kernel_launch(void* const* d_in, const int* in_sizes, int n_in,
                              void* d_out, int out_size){
    (void)in_sizes; (void)n_in; (void)out_size;
    const float* ls  = (const float*)d_in[0];  // logits_student [64,100]
    const float* lt  = (const float*)d_in[1];  // logits_teacher [64,100]
    const int*   tgt = (const int*)  d_in[2];  // target [64]
    float* out = (float*)d_out;

    fused_kernel<<<NBLK, NTHR>>>(ls, lt, tgt, out);
}